// round 11
// baseline (speedup 1.0000x reference)
#include <cuda_runtime.h>
#include <cfloat>

// Problem constants (fixed by the dataset)
#define D        64
#define KCODES   1024
#define TM       128          // rows per CTA
#define TK       128          // codes per chunk
#define NCHUNK   (KCODES / TK)
#define NTILE    (TK / 8)     // 8-code n-tiles per chunk
#define THREADS  256
#define NROWS_MAX 131072

typedef unsigned int u32;

// Scratch (__device__ globals, allocation-free rule)
__device__ float g_en[KCODES];                        // ||e_k||^2, reference order
__device__ __align__(16) float g_ehi[KCODES * D];     // E hi (tf32 values), fragment-packed
__device__ float g_partial[1024];
__device__ int   g_risky_count;
__device__ int   g_risky[NROWS_MAX];

// SMEM layout (bytes)
#define SM_EHI    0            // 32 KB (aliased by z staging before main loop)
#define SM_IDX    32768        // 128 ints
#define SM_RED    33280        // 8 floats
#define SM_TOTAL  33408

__device__ __forceinline__ u32 to_tf32(float v) {
  u32 r; asm("cvt.rna.tf32.f32 %0, %1;" : "=r"(r) : "f"(v)); return r;
}

__device__ __forceinline__ void mma_tf32(float& d0, float& d1, float& d2, float& d3,
                                         u32 a0, u32 a1, u32 a2, u32 a3,
                                         u32 b0, u32 b1) {
  asm volatile(
    "mma.sync.aligned.m16n8k8.row.col.f32.tf32.tf32.f32 "
    "{%0,%1,%2,%3}, {%4,%5,%6,%7}, {%8,%9}, {%0,%1,%2,%3};"
    : "+f"(d0), "+f"(d1), "+f"(d2), "+f"(d3)
    : "r"(a0), "r"(a1), "r"(a2), "r"(a3), "r"(b0), "r"(b1));
}

// Reference-order squared-norm (verified): 4 lanes, (S0+S2)+(S1+S3)
__device__ __forceinline__ float ref_sqnorm_seq(const float* base) {
  float S[4] = {0.f, 0.f, 0.f, 0.f};
  #pragma unroll
  for (int i = 0; i < D / 4; i++)
    #pragma unroll
    for (int j = 0; j < 4; j++) {
      float v = base[4 * i + j];
      S[j] = __fadd_rn(S[j], __fmul_rn(v, v));
    }
  return __fadd_rn(__fadd_rn(S[0], S[2]), __fadd_rn(S[1], S[3]));
}

// ---------------------------------------------------------------------------
// Kernel 0: prep — en (reference order) + E-hi fragment packing + counter reset
// ---------------------------------------------------------------------------
__global__ void vq_prep_kernel(const float* __restrict__ emb) {
  int k = blockIdx.x * blockDim.x + threadIdx.x;
  if (k == 0) g_risky_count = 0;
  if (k >= KCODES) return;
  const int chunk = k >> 7, local = k & 127;
  const int tt = local >> 3, np = local & 7;
  const float* e = emb + (size_t)k * D;

  g_en[k] = ref_sqnorm_seq(e);

  float ehi[D];
  #pragma unroll
  for (int i = 0; i < D; i++)
    ehi[i] = __uint_as_float(to_tf32(e[i]));

  // fragment pack: float2 = { E[tt*8 + l/4][8ks + l%4], E[same][8ks + l%4 + 4] }
  #pragma unroll
  for (int ks = 0; ks < 8; ks++)
    #pragma unroll
    for (int kk = 0; kk < 4; kk++) {
      int l = np * 4 + kk;
      size_t off = (size_t)chunk * 8192 + (size_t)((tt * 8 + ks) * 32 + l) * 2;
      *(float2*)(g_ehi + off) = make_float2(ehi[8 * ks + kk], ehi[8 * ks + kk + 4]);
    }
}

// ---------------------------------------------------------------------------
// Kernel 1: single-pass tf32 mma scores + quantized argmin + risky flagging
// ---------------------------------------------------------------------------
__global__ void __launch_bounds__(THREADS, 2)
vq_main_kernel(const float* __restrict__ z, const float* __restrict__ emb,
               float* __restrict__ out_zq, float* __restrict__ out_idx) {
  extern __shared__ __align__(16) char smem[];
  float2* e_hi  = (float2*)(smem + SM_EHI);
  int*    sidx  = (int*)(smem + SM_IDX);
  float*  sred  = (float*)(smem + SM_RED);
  float*  zstage = (float*)(smem + SM_EHI);   // alias: consumed before E loads

  const int t = threadIdx.x;
  const int w = t >> 5, lane = t & 31;
  const int g = lane >> 2, m = lane & 3;
  const int lr0 = w * 16 + g, lr1 = lr0 + 8;  // this thread's two rows (local)
  const size_t rowBase = (size_t)blockIdx.x * TM;

  // --- stage z tile (raw row-major [128][64]) ---
  {
    const float4* src = (const float4*)(z + rowBase * D);
    float4* dst = (float4*)zstage;
    #pragma unroll
    for (int i = 0; i < 8; i++) dst[t + i * THREADS] = src[t + i * THREADS];
  }
  __syncthreads();

  // --- A-hi fragments (persistent) + reference-order zn via quad shfl ---
  u32 ah0[8], ah1[8], ah2[8], ah3[8];
  float zn0, zn1;
  {
    const float* zr0 = zstage + lr0 * D;
    const float* zr1 = zstage + lr1 * D;
    float S0 = 0.f, S1 = 0.f;          // S_m partial for rows r0, r1
    #pragma unroll
    for (int ks = 0; ks < 8; ks++) {
      float v00 = zr0[8 * ks + m], v01 = zr0[8 * ks + m + 4];
      float v10 = zr1[8 * ks + m], v11 = zr1[8 * ks + m + 4];
      S0 = __fadd_rn(S0, __fmul_rn(v00, v00));
      S0 = __fadd_rn(S0, __fmul_rn(v01, v01));
      S1 = __fadd_rn(S1, __fmul_rn(v10, v10));
      S1 = __fadd_rn(S1, __fmul_rn(v11, v11));
      ah0[ks] = to_tf32(v00); ah2[ks] = to_tf32(v01);
      ah1[ks] = to_tf32(v10); ah3[ks] = to_tf32(v11);
    }
    // zn = (S0+S2)+(S1+S3): quad butterfly, commutative fadd keeps bits equal
    float T0 = __fadd_rn(S0, __shfl_xor_sync(0xFFFFFFFFu, S0, 2));
    zn0 = __fadd_rn(T0, __shfl_xor_sync(0xFFFFFFFFu, T0, 1));
    float T1 = __fadd_rn(S1, __shfl_xor_sync(0xFFFFFFFFu, S1, 2));
    zn1 = __fadd_rn(T1, __shfl_xor_sync(0xFFFFFFFFu, T1, 1));
  }
  __syncthreads();   // z staging fully consumed; smem now free for E

  float min0v = FLT_MAX, min1v = FLT_MAX;   // best quantized d
  float min0s = FLT_MAX, min1s = FLT_MAX;   // second-best (value only)
  int   min0i = 0,       min1i = 0;

  for (int ch = 0; ch < NCHUNK; ch++) {
    // load E chunk (pre-packed fragment image): 32 KB
    {
      const float4* sh = (const float4*)(g_ehi + (size_t)ch * 8192);
      float4* dh = (float4*)e_hi;
      #pragma unroll
      for (int i = 0; i < 8; i++) dh[t + i * THREADS] = sh[t + i * THREADS];
    }
    __syncthreads();

    #pragma unroll
    for (int tt = 0; tt < NTILE; tt++) {
      // single pass: zh . eh
      float d0 = 0.f, d1 = 0.f, d2 = 0.f, d3 = 0.f;
      #pragma unroll
      for (int ks = 0; ks < 8; ks++) {
        float2 b = e_hi[(tt * 8 + ks) * 32 + lane];
        mma_tf32(d0, d1, d2, d3, ah0[ks], ah1[ks], ah2[ks], ah3[ks],
                 __float_as_uint(b.x), __float_as_uint(b.y));
      }

      // epilogue: d-regs map to rows (g,g+8) x cols (2m, 2m+1) of this tile
      const int cb = ch * TK + tt * 8 + 2 * m;
      float2 en2 = __ldg((const float2*)(g_en + cb));
      float dv;
      dv = __fsub_rn(__fadd_rn(zn0, en2.x), __fadd_rn(d0, d0));
      if (dv < min0v) { min0s = min0v; min0v = dv; min0i = cb; }
      else if (dv < min0s) min0s = dv;
      dv = __fsub_rn(__fadd_rn(zn0, en2.y), __fadd_rn(d1, d1));
      if (dv < min0v) { min0s = min0v; min0v = dv; min0i = cb + 1; }
      else if (dv < min0s) min0s = dv;
      dv = __fsub_rn(__fadd_rn(zn1, en2.x), __fadd_rn(d2, d2));
      if (dv < min1v) { min1s = min1v; min1v = dv; min1i = cb; }
      else if (dv < min1s) min1s = dv;
      dv = __fsub_rn(__fadd_rn(zn1, en2.y), __fadd_rn(d3, d3));
      if (dv < min1v) { min1s = min1v; min1v = dv; min1i = cb + 1; }
      else if (dv < min1s) min1s = dv;
    }
    __syncthreads();   // all tiles consumed before next chunk overwrites E
  }

  // --- cross-lane top-2 argmin within each quad (tie -> lowest index) ---
  #pragma unroll
  for (int off = 1; off <= 2; off <<= 1) {
    float ov = __shfl_xor_sync(0xFFFFFFFFu, min0v, off);
    int   oi = __shfl_xor_sync(0xFFFFFFFFu, min0i, off);
    float os = __shfl_xor_sync(0xFFFFFFFFu, min0s, off);
    if (ov < min0v || (ov == min0v && oi < min0i)) {
      min0s = fminf(min0v, os); min0v = ov; min0i = oi;
    } else min0s = fminf(min0s, ov);
    ov = __shfl_xor_sync(0xFFFFFFFFu, min1v, off);
    oi = __shfl_xor_sync(0xFFFFFFFFu, min1i, off);
    os = __shfl_xor_sync(0xFFFFFFFFu, min1s, off);
    if (ov < min1v || (ov == min1v && oi < min1i)) {
      min1s = fminf(min1v, os); min1v = ov; min1i = oi;
    } else min1s = fminf(min1s, ov);
  }

  float contrib = 0.f;
  if (m == 0) {
    sidx[lr0] = min0i; sidx[lr1] = min1i;
    out_idx[rowBase + lr0] = (float)min0i;
    out_idx[rowBase + lr1] = (float)min1i;
    contrib = min0v + min1v;   // quantized d_min values (verified semantics)
    // risky rows: top-2 gap within ~34 grid steps (>>10x max single-pass
    // dot error) -> exact rescore later
    if (min0s - min0v <= min0v * 4e-6f) {
      int p = atomicAdd(&g_risky_count, 1);
      g_risky[p] = (int)(rowBase + lr0);
    }
    if (min1s - min1v <= min1v * 4e-6f) {
      int p = atomicAdd(&g_risky_count, 1);
      g_risky[p] = (int)(rowBase + lr1);
    }
  }
  // warp sum of loss contributions
  #pragma unroll
  for (int o = 16; o > 0; o >>= 1) contrib += __shfl_xor_sync(0xFFFFFFFFu, contrib, o);
  if (lane == 0) sred[w] = contrib;
  __syncthreads();
  if (t == 0) {
    float tot = 0.f;
    #pragma unroll
    for (int i = 0; i < 8; i++) tot += sred[i];
    g_partial[blockIdx.x] = tot;
  }

  // coalesced z_q gather: 16 float4 lanes per row
  for (int j = t; j < TM * (D / 4); j += THREADS) {
    int r2 = j >> 4, p = j & 15;
    ((float4*)(out_zq + (rowBase + r2) * D))[p] =
        ((const float4*)(emb + (size_t)sidx[r2] * D))[p];
  }
}

// ---------------------------------------------------------------------------
// Kernel 1b: exact rescore of risky rows (verified SIMT numerics).
// One warp per row; all 1024 codes; overwrites idx + z_q.
// ---------------------------------------------------------------------------
__global__ void __launch_bounds__(256, 4)
vq_fix_kernel(const float* __restrict__ z, const float* __restrict__ emb,
              float* __restrict__ out_zq, float* __restrict__ out_idx) {
  __shared__ float zrow[8][D];
  const int wl = threadIdx.x >> 5, lane = threadIdx.x & 31;
  const int wg = blockIdx.x * 8 + wl;
  const int nw = gridDim.x * 8;
  const int cnt = g_risky_count;

  for (int i = wg; i < cnt; i += nw) {
    const int row = g_risky[i];
    ((float2*)zrow[wl])[lane] = ((const float2*)(z + (size_t)row * D))[lane];
    __syncwarp();
    // zn in reference order
    float S[4] = {0.f, 0.f, 0.f, 0.f};
    #pragma unroll
    for (int ii = 0; ii < D / 4; ii++)
      #pragma unroll
      for (int j = 0; j < 4; j++) {
        float v = zrow[wl][4 * ii + j];
        S[j] = __fadd_rn(S[j], __fmul_rn(v, v));
      }
    float zn = __fadd_rn(__fadd_rn(S[0], S[2]), __fadd_rn(S[1], S[3]));

    float bestv = FLT_MAX; int besti = 0;
    for (int j = 0; j < KCODES / 32; j++) {
      const int code = j * 32 + lane;
      const float* e = emb + (size_t)code * D;
      float acc = 0.f;
      #pragma unroll
      for (int dd = 0; dd < D; dd++)
        acc = __fmaf_rn(zrow[wl][dd], __ldg(e + dd), acc);
      float dv = __fsub_rn(__fadd_rn(zn, __ldg(&g_en[code])), __fadd_rn(acc, acc));
      if (dv < bestv) { bestv = dv; besti = code; }
    }
    #pragma unroll
    for (int off = 16; off > 0; off >>= 1) {
      float ov = __shfl_xor_sync(0xFFFFFFFFu, bestv, off);
      int   oi = __shfl_xor_sync(0xFFFFFFFFu, besti, off);
      if (ov < bestv || (ov == bestv && oi < besti)) { bestv = ov; besti = oi; }
    }
    if (lane == 0) out_idx[row] = (float)besti;
    if (lane < 16)
      ((float4*)(out_zq + (size_t)row * D))[lane] =
          ((const float4*)(emb + (size_t)besti * D))[lane];
    __syncwarp();
  }
}

// ---------------------------------------------------------------------------
// Kernel 2: deterministic loss reduction (double accumulation)
// loss = 1.25 * sum(d_min) / (N*D)
// ---------------------------------------------------------------------------
__global__ void vq_finish_kernel(float* __restrict__ out_loss, int nb, long long nd) {
  int t = threadIdx.x;
  double v = (t < nb) ? (double)g_partial[t] : 0.0;
  #pragma unroll
  for (int o = 16; o > 0; o >>= 1) v += __shfl_xor_sync(0xFFFFFFFFu, v, o);
  __shared__ double red[32];
  if ((t & 31) == 0) red[t >> 5] = v;
  __syncthreads();
  if (t < 32) {
    double w = (t < (int)(blockDim.x >> 5)) ? red[t] : 0.0;
    #pragma unroll
    for (int o = 16; o > 0; o >>= 1) w += __shfl_xor_sync(0xFFFFFFFFu, w, o);
    if (t == 0) out_loss[0] = (float)(1.25 * w / (double)nd);
  }
}

// ---------------------------------------------------------------------------
extern "C" void kernel_launch(void* const* d_in, const int* in_sizes, int n_in,
                              void* d_out, int out_size) {
  const float* z   = (const float*)d_in[0];   // [N,1,64] fp32
  const float* emb = (const float*)d_in[1];   // [1024,64] fp32
  float* out = (float*)d_out;

  const int N = in_sizes[0] / D;              // 131072
  float* out_zq   = out;                      // [N*D]
  float* out_idx  = out + (size_t)N * D;      // [N] (indices as float)
  float* out_loss = out_idx + N;              // [1]

  vq_prep_kernel<<<(KCODES + 127) / 128, 128>>>(emb);

  cudaFuncSetAttribute(vq_main_kernel,
                       cudaFuncAttributeMaxDynamicSharedMemorySize, SM_TOTAL);
  vq_main_kernel<<<N / TM, THREADS, SM_TOTAL>>>(z, emb, out_zq, out_idx);

  vq_fix_kernel<<<128, 256>>>(z, emb, out_zq, out_idx);

  vq_finish_kernel<<<1, 1024>>>(out_loss, N / TM, (long long)N * D);
}

// round 12
// speedup vs baseline: 1.0056x; 1.0056x over previous
#include <cuda_runtime.h>
#include <cfloat>

// Problem constants (fixed by the dataset)
#define D        64
#define KCODES   1024
#define TM       128          // rows per CTA
#define TK       128          // codes per chunk
#define NCHUNK   (KCODES / TK)
#define NTILE    (TK / 8)     // 8-code n-tiles per chunk
#define THREADS  256
#define NROWS_MAX 131072

typedef unsigned int u32;

// Scratch (__device__ globals, allocation-free rule)
__device__ float g_en[KCODES];                        // ||e_k||^2, reference order
__device__ __align__(16) float g_ehi[KCODES * D];     // E hi (tf32 values), fragment-packed
__device__ float g_partial[1024];
__device__ int   g_risky_count;
__device__ int   g_risky[NROWS_MAX];

// SMEM layout (bytes): two E-chunk buffers (double-buffered via cp.async)
#define SM_EA     0            // 32 KB buffer A
#define SM_EB     32768        // 32 KB buffer B (aliased by z staging at start)
#define SM_IDX    65536        // 128 ints
#define SM_RED    66048        // 8 floats
#define SM_TOTAL  66176

__device__ __forceinline__ u32 to_tf32(float v) {
  u32 r; asm("cvt.rna.tf32.f32 %0, %1;" : "=r"(r) : "f"(v)); return r;
}
__device__ __forceinline__ void cp_async16(u32 saddr, const void* gptr) {
  asm volatile("cp.async.cg.shared.global [%0], [%1], 16;"
               :: "r"(saddr), "l"(gptr) : "memory");
}
#define CP_COMMIT() asm volatile("cp.async.commit_group;" ::: "memory")
#define CP_WAIT(n)  asm volatile("cp.async.wait_group %0;" :: "n"(n) : "memory")

__device__ __forceinline__ void mma_tf32(float& d0, float& d1, float& d2, float& d3,
                                         u32 a0, u32 a1, u32 a2, u32 a3,
                                         u32 b0, u32 b1) {
  asm volatile(
    "mma.sync.aligned.m16n8k8.row.col.f32.tf32.tf32.f32 "
    "{%0,%1,%2,%3}, {%4,%5,%6,%7}, {%8,%9}, {%0,%1,%2,%3};"
    : "+f"(d0), "+f"(d1), "+f"(d2), "+f"(d3)
    : "r"(a0), "r"(a1), "r"(a2), "r"(a3), "r"(b0), "r"(b1));
}

// Reference-order squared-norm (verified): 4 lanes, (S0+S2)+(S1+S3)
__device__ __forceinline__ float ref_sqnorm_seq(const float* base) {
  float S[4] = {0.f, 0.f, 0.f, 0.f};
  #pragma unroll
  for (int i = 0; i < D / 4; i++)
    #pragma unroll
    for (int j = 0; j < 4; j++) {
      float v = base[4 * i + j];
      S[j] = __fadd_rn(S[j], __fmul_rn(v, v));
    }
  return __fadd_rn(__fadd_rn(S[0], S[2]), __fadd_rn(S[1], S[3]));
}

// ---------------------------------------------------------------------------
// Kernel 0: prep — en (reference order) + E-hi fragment packing + counter reset
// ---------------------------------------------------------------------------
__global__ void vq_prep_kernel(const float* __restrict__ emb) {
  int k = blockIdx.x * blockDim.x + threadIdx.x;
  if (k == 0) g_risky_count = 0;
  if (k >= KCODES) return;
  const int chunk = k >> 7, local = k & 127;
  const int tt = local >> 3, np = local & 7;
  const float* e = emb + (size_t)k * D;

  g_en[k] = ref_sqnorm_seq(e);

  float ehi[D];
  #pragma unroll
  for (int i = 0; i < D; i++)
    ehi[i] = __uint_as_float(to_tf32(e[i]));

  // fragment pack: float2 = { E[tt*8 + l/4][8ks + l%4], E[same][8ks + l%4 + 4] }
  #pragma unroll
  for (int ks = 0; ks < 8; ks++)
    #pragma unroll
    for (int kk = 0; kk < 4; kk++) {
      int l = np * 4 + kk;
      size_t off = (size_t)chunk * 8192 + (size_t)((tt * 8 + ks) * 32 + l) * 2;
      *(float2*)(g_ehi + off) = make_float2(ehi[8 * ks + kk], ehi[8 * ks + kk + 4]);
    }
}

// ---------------------------------------------------------------------------
// Kernel 1: single-pass tf32 mma scores, double-buffered E via cp.async
// ---------------------------------------------------------------------------
__global__ void __launch_bounds__(THREADS, 2)
vq_main_kernel(const float* __restrict__ z, const float* __restrict__ emb,
               float* __restrict__ out_zq, float* __restrict__ out_idx) {
  extern __shared__ __align__(16) char smem[];
  int*    sidx  = (int*)(smem + SM_IDX);
  float*  sred  = (float*)(smem + SM_RED);
  float*  zstage = (float*)(smem + SM_EB);   // alias buf B: consumed pre-loop

  const int t = threadIdx.x;
  const int w = t >> 5, lane = t & 31;
  const int g = lane >> 2, m = lane & 3;
  const int lr0 = w * 16 + g, lr1 = lr0 + 8;  // this thread's two rows (local)
  const size_t rowBase = (size_t)blockIdx.x * TM;

  char* cur = smem + SM_EA;
  char* oth = smem + SM_EB;

  // --- prologue: async-load chunk 0 into buffer A (overlaps z processing) ---
  {
    u32 sa = (u32)__cvta_generic_to_shared(cur) + t * 16;
    const float4* gp = (const float4*)g_ehi + t;
    #pragma unroll
    for (int i = 0; i < 8; i++)
      cp_async16(sa + i * THREADS * 16, gp + i * THREADS);
    CP_COMMIT();
  }

  // --- stage z tile (raw row-major [128][64]) into buffer B ---
  {
    const float4* src = (const float4*)(z + rowBase * D);
    float4* dst = (float4*)zstage;
    #pragma unroll
    for (int i = 0; i < 8; i++) dst[t + i * THREADS] = src[t + i * THREADS];
  }
  __syncthreads();

  // --- A-hi fragments (persistent) + reference-order zn via quad shfl ---
  u32 ah0[8], ah1[8], ah2[8], ah3[8];
  float zn0, zn1;
  {
    const float* zr0 = zstage + lr0 * D;
    const float* zr1 = zstage + lr1 * D;
    float S0 = 0.f, S1 = 0.f;          // S_m partial for rows r0, r1
    #pragma unroll
    for (int ks = 0; ks < 8; ks++) {
      float v00 = zr0[8 * ks + m], v01 = zr0[8 * ks + m + 4];
      float v10 = zr1[8 * ks + m], v11 = zr1[8 * ks + m + 4];
      S0 = __fadd_rn(S0, __fmul_rn(v00, v00));
      S0 = __fadd_rn(S0, __fmul_rn(v01, v01));
      S1 = __fadd_rn(S1, __fmul_rn(v10, v10));
      S1 = __fadd_rn(S1, __fmul_rn(v11, v11));
      ah0[ks] = to_tf32(v00); ah2[ks] = to_tf32(v01);
      ah1[ks] = to_tf32(v10); ah3[ks] = to_tf32(v11);
    }
    // zn = (S0+S2)+(S1+S3): quad butterfly, commutative fadd keeps bits equal
    float T0 = __fadd_rn(S0, __shfl_xor_sync(0xFFFFFFFFu, S0, 2));
    zn0 = __fadd_rn(T0, __shfl_xor_sync(0xFFFFFFFFu, T0, 1));
    float T1 = __fadd_rn(S1, __shfl_xor_sync(0xFFFFFFFFu, S1, 2));
    zn1 = __fadd_rn(T1, __shfl_xor_sync(0xFFFFFFFFu, T1, 1));
  }
  __syncthreads();   // z staging fully consumed; buffer B free for prefetch

  float min0v = FLT_MAX, min1v = FLT_MAX;   // best quantized d
  float min0s = FLT_MAX, min1s = FLT_MAX;   // second-best (value only)
  int   min0i = 0,       min1i = 0;

  for (int ch = 0; ch < NCHUNK; ch++) {
    // prefetch next chunk into the other buffer; wait for current chunk
    if (ch + 1 < NCHUNK) {
      u32 sa = (u32)__cvta_generic_to_shared(oth) + t * 16;
      const float4* gp = (const float4*)(g_ehi + (size_t)(ch + 1) * 8192) + t;
      #pragma unroll
      for (int i = 0; i < 8; i++)
        cp_async16(sa + i * THREADS * 16, gp + i * THREADS);
      CP_COMMIT();
      CP_WAIT(1);
    } else {
      CP_WAIT(0);
    }
    __syncthreads();

    const float2* e_hi = (const float2*)cur;
    #pragma unroll
    for (int tt = 0; tt < NTILE; tt++) {
      // B-hi fragments prefetched into regs (no exposed LDS->HMMA latency)
      u32 bh0[8], bh1[8];
      #pragma unroll
      for (int ks = 0; ks < 8; ks++) {
        float2 b = e_hi[(tt * 8 + ks) * 32 + lane];
        bh0[ks] = __float_as_uint(b.x);
        bh1[ks] = __float_as_uint(b.y);
      }
      // single pass: zh . eh
      float d0 = 0.f, d1 = 0.f, d2 = 0.f, d3 = 0.f;
      #pragma unroll
      for (int ks = 0; ks < 8; ks++)
        mma_tf32(d0, d1, d2, d3, ah0[ks], ah1[ks], ah2[ks], ah3[ks],
                 bh0[ks], bh1[ks]);

      // epilogue: d-regs map to rows (g,g+8) x cols (2m, 2m+1) of this tile
      const int cb = ch * TK + tt * 8 + 2 * m;
      float2 en2 = __ldg((const float2*)(g_en + cb));
      float dv;
      dv = __fsub_rn(__fadd_rn(zn0, en2.x), __fadd_rn(d0, d0));
      if (dv < min0v) { min0s = min0v; min0v = dv; min0i = cb; }
      else if (dv < min0s) min0s = dv;
      dv = __fsub_rn(__fadd_rn(zn0, en2.y), __fadd_rn(d1, d1));
      if (dv < min0v) { min0s = min0v; min0v = dv; min0i = cb + 1; }
      else if (dv < min0s) min0s = dv;
      dv = __fsub_rn(__fadd_rn(zn1, en2.x), __fadd_rn(d2, d2));
      if (dv < min1v) { min1s = min1v; min1v = dv; min1i = cb; }
      else if (dv < min1s) min1s = dv;
      dv = __fsub_rn(__fadd_rn(zn1, en2.y), __fadd_rn(d3, d3));
      if (dv < min1v) { min1s = min1v; min1v = dv; min1i = cb + 1; }
      else if (dv < min1s) min1s = dv;
    }
    __syncthreads();   // all tiles consumed before this buffer is refilled
    char* tmp = cur; cur = oth; oth = tmp;
  }

  // --- cross-lane top-2 argmin within each quad (tie -> lowest index) ---
  #pragma unroll
  for (int off = 1; off <= 2; off <<= 1) {
    float ov = __shfl_xor_sync(0xFFFFFFFFu, min0v, off);
    int   oi = __shfl_xor_sync(0xFFFFFFFFu, min0i, off);
    float os = __shfl_xor_sync(0xFFFFFFFFu, min0s, off);
    if (ov < min0v || (ov == min0v && oi < min0i)) {
      min0s = fminf(min0v, os); min0v = ov; min0i = oi;
    } else min0s = fminf(min0s, ov);
    ov = __shfl_xor_sync(0xFFFFFFFFu, min1v, off);
    oi = __shfl_xor_sync(0xFFFFFFFFu, min1i, off);
    os = __shfl_xor_sync(0xFFFFFFFFu, min1s, off);
    if (ov < min1v || (ov == min1v && oi < min1i)) {
      min1s = fminf(min1v, os); min1v = ov; min1i = oi;
    } else min1s = fminf(min1s, ov);
  }

  float contrib = 0.f;
  if (m == 0) {
    sidx[lr0] = min0i; sidx[lr1] = min1i;
    out_idx[rowBase + lr0] = (float)min0i;
    out_idx[rowBase + lr1] = (float)min1i;
    contrib = min0v + min1v;   // quantized d_min values (verified semantics)
    // risky rows: top-2 gap within ~34 grid steps (>>10x max single-pass
    // dot error) -> exact rescore later  [validated in round 11]
    if (min0s - min0v <= min0v * 4e-6f) {
      int p = atomicAdd(&g_risky_count, 1);
      g_risky[p] = (int)(rowBase + lr0);
    }
    if (min1s - min1v <= min1v * 4e-6f) {
      int p = atomicAdd(&g_risky_count, 1);
      g_risky[p] = (int)(rowBase + lr1);
    }
  }
  // warp sum of loss contributions
  #pragma unroll
  for (int o = 16; o > 0; o >>= 1) contrib += __shfl_xor_sync(0xFFFFFFFFu, contrib, o);
  if (lane == 0) sred[w] = contrib;
  __syncthreads();
  if (t == 0) {
    float tot = 0.f;
    #pragma unroll
    for (int i = 0; i < 8; i++) tot += sred[i];
    g_partial[blockIdx.x] = tot;
  }

  // coalesced z_q gather: 16 float4 lanes per row
  for (int j = t; j < TM * (D / 4); j += THREADS) {
    int r2 = j >> 4, p = j & 15;
    ((float4*)(out_zq + (rowBase + r2) * D))[p] =
        ((const float4*)(emb + (size_t)sidx[r2] * D))[p];
  }
}

// ---------------------------------------------------------------------------
// Kernel 1b: exact rescore of risky rows (verified SIMT numerics).
// One warp per row; all 1024 codes; overwrites idx + z_q.
// ---------------------------------------------------------------------------
__global__ void __launch_bounds__(256, 4)
vq_fix_kernel(const float* __restrict__ z, const float* __restrict__ emb,
              float* __restrict__ out_zq, float* __restrict__ out_idx) {
  __shared__ float zrow[8][D];
  const int wl = threadIdx.x >> 5, lane = threadIdx.x & 31;
  const int wg = blockIdx.x * 8 + wl;
  const int nw = gridDim.x * 8;
  const int cnt = g_risky_count;

  for (int i = wg; i < cnt; i += nw) {
    const int row = g_risky[i];
    ((float2*)zrow[wl])[lane] = ((const float2*)(z + (size_t)row * D))[lane];
    __syncwarp();
    // zn in reference order
    float S[4] = {0.f, 0.f, 0.f, 0.f};
    #pragma unroll
    for (int ii = 0; ii < D / 4; ii++)
      #pragma unroll
      for (int j = 0; j < 4; j++) {
        float v = zrow[wl][4 * ii + j];
        S[j] = __fadd_rn(S[j], __fmul_rn(v, v));
      }
    float zn = __fadd_rn(__fadd_rn(S[0], S[2]), __fadd_rn(S[1], S[3]));

    float bestv = FLT_MAX; int besti = 0;
    for (int j = 0; j < KCODES / 32; j++) {
      const int code = j * 32 + lane;
      const float* e = emb + (size_t)code * D;
      float acc = 0.f;
      #pragma unroll
      for (int dd = 0; dd < D; dd++)
        acc = __fmaf_rn(zrow[wl][dd], __ldg(e + dd), acc);
      float dv = __fsub_rn(__fadd_rn(zn, __ldg(&g_en[code])), __fadd_rn(acc, acc));
      if (dv < bestv) { bestv = dv; besti = code; }
    }
    #pragma unroll
    for (int off = 16; off > 0; off >>= 1) {
      float ov = __shfl_xor_sync(0xFFFFFFFFu, bestv, off);
      int   oi = __shfl_xor_sync(0xFFFFFFFFu, besti, off);
      if (ov < bestv || (ov == bestv && oi < besti)) { bestv = ov; besti = oi; }
    }
    if (lane == 0) out_idx[row] = (float)besti;
    if (lane < 16)
      ((float4*)(out_zq + (size_t)row * D))[lane] =
          ((const float4*)(emb + (size_t)besti * D))[lane];
    __syncwarp();
  }
}

// ---------------------------------------------------------------------------
// Kernel 2: deterministic loss reduction (double accumulation)
// loss = 1.25 * sum(d_min) / (N*D)
// ---------------------------------------------------------------------------
__global__ void vq_finish_kernel(float* __restrict__ out_loss, int nb, long long nd) {
  int t = threadIdx.x;
  double v = (t < nb) ? (double)g_partial[t] : 0.0;
  #pragma unroll
  for (int o = 16; o > 0; o >>= 1) v += __shfl_xor_sync(0xFFFFFFFFu, v, o);
  __shared__ double red[32];
  if ((t & 31) == 0) red[t >> 5] = v;
  __syncthreads();
  if (t < 32) {
    double w = (t < (int)(blockDim.x >> 5)) ? red[t] : 0.0;
    #pragma unroll
    for (int o = 16; o > 0; o >>= 1) w += __shfl_xor_sync(0xFFFFFFFFu, w, o);
    if (t == 0) out_loss[0] = (float)(1.25 * w / (double)nd);
  }
}

// ---------------------------------------------------------------------------
extern "C" void kernel_launch(void* const* d_in, const int* in_sizes, int n_in,
                              void* d_out, int out_size) {
  const float* z   = (const float*)d_in[0];   // [N,1,64] fp32
  const float* emb = (const float*)d_in[1];   // [1024,64] fp32
  float* out = (float*)d_out;

  const int N = in_sizes[0] / D;              // 131072
  float* out_zq   = out;                      // [N*D]
  float* out_idx  = out + (size_t)N * D;      // [N] (indices as float)
  float* out_loss = out_idx + N;              // [1]

  vq_prep_kernel<<<(KCODES + 127) / 128, 128>>>(emb);

  cudaFuncSetAttribute(vq_main_kernel,
                       cudaFuncAttributeMaxDynamicSharedMemorySize, SM_TOTAL);
  vq_main_kernel<<<N / TM, THREADS, SM_TOTAL>>>(z, emb, out_zq, out_idx);

  vq_fix_kernel<<<128, 256>>>(z, emb, out_zq, out_idx);

  vq_finish_kernel<<<1, 1024>>>(out_loss, N / TM, (long long)N * D);
}

// round 13
// speedup vs baseline: 12.4076x; 12.3389x over previous
#include <cuda_runtime.h>
#include <cfloat>

// Problem constants (fixed by the dataset)
#define D        64
#define KCODES   1024
#define TM       128          // rows per CTA
#define TK       128          // codes per chunk
#define NCHUNK   (KCODES / TK)
#define NTILE    (TK / 8)     // 8-code n-tiles per chunk
#define THREADS  256
#define NROWS_MAX 131072

typedef unsigned int u32;

// Scratch (__device__ globals, allocation-free rule)
__device__ float g_en[KCODES];                        // ||e_k||^2, reference order
__device__ __align__(16) float g_ehi[KCODES * D];     // E hi (tf32 values), fragment-packed
__device__ float g_partial[1024];
__device__ int   g_risky_count;
__device__ int   g_risky[NROWS_MAX];

// SMEM layout (bytes): two E-chunk buffers (double-buffered via cp.async)
#define SM_EA     0            // 32 KB buffer A
#define SM_EB     32768        // 32 KB buffer B (aliased by z staging at start)
#define SM_IDX    65536        // 128 ints
#define SM_RED    66048        // 8 floats
#define SM_TOTAL  66176

__device__ __forceinline__ u32 to_tf32(float v) {
  u32 r; asm("cvt.rna.tf32.f32 %0, %1;" : "=r"(r) : "f"(v)); return r;
}
__device__ __forceinline__ void cp_async16(u32 saddr, const void* gptr) {
  asm volatile("cp.async.cg.shared.global [%0], [%1], 16;"
               :: "r"(saddr), "l"(gptr) : "memory");
}
#define CP_COMMIT() asm volatile("cp.async.commit_group;" ::: "memory")
#define CP_WAIT(n)  asm volatile("cp.async.wait_group %0;" :: "n"(n) : "memory")

__device__ __forceinline__ void mma_tf32(float& d0, float& d1, float& d2, float& d3,
                                         u32 a0, u32 a1, u32 a2, u32 a3,
                                         u32 b0, u32 b1) {
  asm volatile(
    "mma.sync.aligned.m16n8k8.row.col.f32.tf32.tf32.f32 "
    "{%0,%1,%2,%3}, {%4,%5,%6,%7}, {%8,%9}, {%0,%1,%2,%3};"
    : "+f"(d0), "+f"(d1), "+f"(d2), "+f"(d3)
    : "r"(a0), "r"(a1), "r"(a2), "r"(a3), "r"(b0), "r"(b1));
}

// Reference-order squared-norm (verified): 4 lanes, (S0+S2)+(S1+S3)
__device__ __forceinline__ float ref_sqnorm_seq(const float* base) {
  float S[4] = {0.f, 0.f, 0.f, 0.f};
  #pragma unroll
  for (int i = 0; i < D / 4; i++)
    #pragma unroll
    for (int j = 0; j < 4; j++) {
      float v = base[4 * i + j];
      S[j] = __fadd_rn(S[j], __fmul_rn(v, v));
    }
  return __fadd_rn(__fadd_rn(S[0], S[2]), __fadd_rn(S[1], S[3]));
}

// ---------------------------------------------------------------------------
// Kernel 0: prep — en (reference order) + E-hi fragment packing + counter reset
// ---------------------------------------------------------------------------
__global__ void vq_prep_kernel(const float* __restrict__ emb) {
  int k = blockIdx.x * blockDim.x + threadIdx.x;
  if (k == 0) g_risky_count = 0;
  if (k >= KCODES) return;
  const int chunk = k >> 7, local = k & 127;
  const int tt = local >> 3, np = local & 7;
  const float* e = emb + (size_t)k * D;

  g_en[k] = ref_sqnorm_seq(e);

  float ehi[D];
  #pragma unroll
  for (int i = 0; i < D; i++)
    ehi[i] = __uint_as_float(to_tf32(e[i]));

  // fragment pack: float2 = { E[tt*8 + l/4][8ks + l%4], E[same][8ks + l%4 + 4] }
  #pragma unroll
  for (int ks = 0; ks < 8; ks++)
    #pragma unroll
    for (int kk = 0; kk < 4; kk++) {
      int l = np * 4 + kk;
      size_t off = (size_t)chunk * 8192 + (size_t)((tt * 8 + ks) * 32 + l) * 2;
      *(float2*)(g_ehi + off) = make_float2(ehi[8 * ks + kk], ehi[8 * ks + kk + 4]);
    }
}

// ---------------------------------------------------------------------------
// Kernel 1: single-pass tf32 mma scores, double-buffered E via cp.async
// (unchanged from round 12 for clean attribution)
// ---------------------------------------------------------------------------
__global__ void __launch_bounds__(THREADS, 2)
vq_main_kernel(const float* __restrict__ z, const float* __restrict__ emb,
               float* __restrict__ out_zq, float* __restrict__ out_idx) {
  extern __shared__ __align__(16) char smem[];
  int*    sidx  = (int*)(smem + SM_IDX);
  float*  sred  = (float*)(smem + SM_RED);
  float*  zstage = (float*)(smem + SM_EB);   // alias buf B: consumed pre-loop

  const int t = threadIdx.x;
  const int w = t >> 5, lane = t & 31;
  const int g = lane >> 2, m = lane & 3;
  const int lr0 = w * 16 + g, lr1 = lr0 + 8;  // this thread's two rows (local)
  const size_t rowBase = (size_t)blockIdx.x * TM;

  char* cur = smem + SM_EA;
  char* oth = smem + SM_EB;

  // --- prologue: async-load chunk 0 into buffer A (overlaps z processing) ---
  {
    u32 sa = (u32)__cvta_generic_to_shared(cur) + t * 16;
    const float4* gp = (const float4*)g_ehi + t;
    #pragma unroll
    for (int i = 0; i < 8; i++)
      cp_async16(sa + i * THREADS * 16, gp + i * THREADS);
    CP_COMMIT();
  }

  // --- stage z tile (raw row-major [128][64]) into buffer B ---
  {
    const float4* src = (const float4*)(z + rowBase * D);
    float4* dst = (float4*)zstage;
    #pragma unroll
    for (int i = 0; i < 8; i++) dst[t + i * THREADS] = src[t + i * THREADS];
  }
  __syncthreads();

  // --- A-hi fragments (persistent) + reference-order zn via quad shfl ---
  u32 ah0[8], ah1[8], ah2[8], ah3[8];
  float zn0, zn1;
  {
    const float* zr0 = zstage + lr0 * D;
    const float* zr1 = zstage + lr1 * D;
    float S0 = 0.f, S1 = 0.f;          // S_m partial for rows r0, r1
    #pragma unroll
    for (int ks = 0; ks < 8; ks++) {
      float v00 = zr0[8 * ks + m], v01 = zr0[8 * ks + m + 4];
      float v10 = zr1[8 * ks + m], v11 = zr1[8 * ks + m + 4];
      S0 = __fadd_rn(S0, __fmul_rn(v00, v00));
      S0 = __fadd_rn(S0, __fmul_rn(v01, v01));
      S1 = __fadd_rn(S1, __fmul_rn(v10, v10));
      S1 = __fadd_rn(S1, __fmul_rn(v11, v11));
      ah0[ks] = to_tf32(v00); ah2[ks] = to_tf32(v01);
      ah1[ks] = to_tf32(v10); ah3[ks] = to_tf32(v11);
    }
    // zn = (S0+S2)+(S1+S3): quad butterfly, commutative fadd keeps bits equal
    float T0 = __fadd_rn(S0, __shfl_xor_sync(0xFFFFFFFFu, S0, 2));
    zn0 = __fadd_rn(T0, __shfl_xor_sync(0xFFFFFFFFu, T0, 1));
    float T1 = __fadd_rn(S1, __shfl_xor_sync(0xFFFFFFFFu, S1, 2));
    zn1 = __fadd_rn(T1, __shfl_xor_sync(0xFFFFFFFFu, T1, 1));
  }
  __syncthreads();   // z staging fully consumed; buffer B free for prefetch

  float min0v = FLT_MAX, min1v = FLT_MAX;   // best quantized d
  float min0s = FLT_MAX, min1s = FLT_MAX;   // second-best (value only)
  int   min0i = 0,       min1i = 0;

  for (int ch = 0; ch < NCHUNK; ch++) {
    // prefetch next chunk into the other buffer; wait for current chunk
    if (ch + 1 < NCHUNK) {
      u32 sa = (u32)__cvta_generic_to_shared(oth) + t * 16;
      const float4* gp = (const float4*)(g_ehi + (size_t)(ch + 1) * 8192) + t;
      #pragma unroll
      for (int i = 0; i < 8; i++)
        cp_async16(sa + i * THREADS * 16, gp + i * THREADS);
      CP_COMMIT();
      CP_WAIT(1);
    } else {
      CP_WAIT(0);
    }
    __syncthreads();

    const float2* e_hi = (const float2*)cur;
    #pragma unroll
    for (int tt = 0; tt < NTILE; tt++) {
      // B-hi fragments prefetched into regs (no exposed LDS->HMMA latency)
      u32 bh0[8], bh1[8];
      #pragma unroll
      for (int ks = 0; ks < 8; ks++) {
        float2 b = e_hi[(tt * 8 + ks) * 32 + lane];
        bh0[ks] = __float_as_uint(b.x);
        bh1[ks] = __float_as_uint(b.y);
      }
      // single pass: zh . eh
      float d0 = 0.f, d1 = 0.f, d2 = 0.f, d3 = 0.f;
      #pragma unroll
      for (int ks = 0; ks < 8; ks++)
        mma_tf32(d0, d1, d2, d3, ah0[ks], ah1[ks], ah2[ks], ah3[ks],
                 bh0[ks], bh1[ks]);

      // epilogue: d-regs map to rows (g,g+8) x cols (2m, 2m+1) of this tile
      const int cb = ch * TK + tt * 8 + 2 * m;
      float2 en2 = __ldg((const float2*)(g_en + cb));
      float dv;
      dv = __fsub_rn(__fadd_rn(zn0, en2.x), __fadd_rn(d0, d0));
      if (dv < min0v) { min0s = min0v; min0v = dv; min0i = cb; }
      else if (dv < min0s) min0s = dv;
      dv = __fsub_rn(__fadd_rn(zn0, en2.y), __fadd_rn(d1, d1));
      if (dv < min0v) { min0s = min0v; min0v = dv; min0i = cb + 1; }
      else if (dv < min0s) min0s = dv;
      dv = __fsub_rn(__fadd_rn(zn1, en2.x), __fadd_rn(d2, d2));
      if (dv < min1v) { min1s = min1v; min1v = dv; min1i = cb; }
      else if (dv < min1s) min1s = dv;
      dv = __fsub_rn(__fadd_rn(zn1, en2.y), __fadd_rn(d3, d3));
      if (dv < min1v) { min1s = min1v; min1v = dv; min1i = cb + 1; }
      else if (dv < min1s) min1s = dv;
    }
    __syncthreads();   // all tiles consumed before this buffer is refilled
    char* tmp = cur; cur = oth; oth = tmp;
  }

  // --- cross-lane top-2 argmin within each quad (tie -> lowest index) ---
  #pragma unroll
  for (int off = 1; off <= 2; off <<= 1) {
    float ov = __shfl_xor_sync(0xFFFFFFFFu, min0v, off);
    int   oi = __shfl_xor_sync(0xFFFFFFFFu, min0i, off);
    float os = __shfl_xor_sync(0xFFFFFFFFu, min0s, off);
    if (ov < min0v || (ov == min0v && oi < min0i)) {
      min0s = fminf(min0v, os); min0v = ov; min0i = oi;
    } else min0s = fminf(min0s, ov);
    ov = __shfl_xor_sync(0xFFFFFFFFu, min1v, off);
    oi = __shfl_xor_sync(0xFFFFFFFFu, min1i, off);
    os = __shfl_xor_sync(0xFFFFFFFFu, min1s, off);
    if (ov < min1v || (ov == min1v && oi < min1i)) {
      min1s = fminf(min1v, os); min1v = ov; min1i = oi;
    } else min1s = fminf(min1s, ov);
  }

  float contrib = 0.f;
  if (m == 0) {
    sidx[lr0] = min0i; sidx[lr1] = min1i;
    out_idx[rowBase + lr0] = (float)min0i;
    out_idx[rowBase + lr1] = (float)min1i;
    contrib = min0v + min1v;   // quantized d_min values (verified semantics)
    // risky rows: top-2 gap within 4e-5 ABSOLUTE (~5.3 grid steps = 7.6 sigma
    // of the single-pass d-difference error) -> exact rescore later
    if (min0s - min0v <= 4e-5f) {
      int p = atomicAdd(&g_risky_count, 1);
      g_risky[p] = (int)(rowBase + lr0);
    }
    if (min1s - min1v <= 4e-5f) {
      int p = atomicAdd(&g_risky_count, 1);
      g_risky[p] = (int)(rowBase + lr1);
    }
  }
  // warp sum of loss contributions
  #pragma unroll
  for (int o = 16; o > 0; o >>= 1) contrib += __shfl_xor_sync(0xFFFFFFFFu, contrib, o);
  if (lane == 0) sred[w] = contrib;
  __syncthreads();
  if (t == 0) {
    float tot = 0.f;
    #pragma unroll
    for (int i = 0; i < 8; i++) tot += sred[i];
    g_partial[blockIdx.x] = tot;
  }

  // coalesced z_q gather: 16 float4 lanes per row
  for (int j = t; j < TM * (D / 4); j += THREADS) {
    int r2 = j >> 4, p = j & 15;
    ((float4*)(out_zq + (rowBase + r2) * D))[p] =
        ((const float4*)(emb + (size_t)sidx[r2] * D))[p];
  }
}

// ---------------------------------------------------------------------------
// Kernel 1b: exact rescore of risky rows — COALESCED version.
// One warp per row. Quad q handles code c0+q; lane m owns dims [16m,16m+16)
// via 4x LDG.128 (warp covers 8 contiguous 256B e-rows). Exact fp32 FMA dot,
// quad shfl-reduce, quantized d, tie -> lowest index.
// ---------------------------------------------------------------------------
__global__ void __launch_bounds__(256, 4)
vq_fix_kernel(const float* __restrict__ z, const float* __restrict__ emb,
              float* __restrict__ out_zq, float* __restrict__ out_idx) {
  __shared__ float zrow[8][D];
  const int wl = threadIdx.x >> 5, lane = threadIdx.x & 31;
  const int q = lane >> 2, m = lane & 3;
  const int wg = blockIdx.x * 8 + wl;
  const int nw = gridDim.x * 8;
  const int cnt = g_risky_count;

  for (int i = wg; i < cnt; i += nw) {
    const int row = g_risky[i];
    ((float2*)zrow[wl])[lane] = ((const float2*)(z + (size_t)row * D))[lane];
    __syncwarp();

    // zn in reference order (verified)
    const float zn = ref_sqnorm_seq(zrow[wl]);

    // this lane's 16-dim z slice
    float zf[16];
    #pragma unroll
    for (int d2 = 0; d2 < 16; d2++) zf[d2] = zrow[wl][m * 16 + d2];

    float bestv = FLT_MAX; int besti = 0;
    for (int c0 = 0; c0 < KCODES; c0 += 8) {
      const int code = c0 + q;
      const float4* ep = (const float4*)(emb + (size_t)code * D + m * 16);
      float p = 0.f;
      #pragma unroll
      for (int v4 = 0; v4 < 4; v4++) {
        float4 ev = __ldg(ep + v4);
        p = __fmaf_rn(zf[v4 * 4 + 0], ev.x, p);
        p = __fmaf_rn(zf[v4 * 4 + 1], ev.y, p);
        p = __fmaf_rn(zf[v4 * 4 + 2], ev.z, p);
        p = __fmaf_rn(zf[v4 * 4 + 3], ev.w, p);
      }
      // quad reduce -> full dot in all 4 lanes
      p += __shfl_xor_sync(0xFFFFFFFFu, p, 1);
      p += __shfl_xor_sync(0xFFFFFFFFu, p, 2);
      float dv = __fsub_rn(__fadd_rn(zn, __ldg(&g_en[code])), __fadd_rn(p, p));
      if (dv < bestv) { bestv = dv; besti = code; }  // codes ascending per quad
    }
    // reduce the 8 quad minima (tie -> lowest index)
    #pragma unroll
    for (int off = 4; off <= 16; off <<= 1) {
      float ov = __shfl_xor_sync(0xFFFFFFFFu, bestv, off);
      int   oi = __shfl_xor_sync(0xFFFFFFFFu, besti, off);
      if (ov < bestv || (ov == bestv && oi < besti)) { bestv = ov; besti = oi; }
    }
    if (lane == 0) out_idx[row] = (float)besti;
    if (lane < 16)
      ((float4*)(out_zq + (size_t)row * D))[lane] =
          ((const float4*)(emb + (size_t)besti * D))[lane];
    __syncwarp();
  }
}

// ---------------------------------------------------------------------------
// Kernel 2: deterministic loss reduction (double accumulation)
// loss = 1.25 * sum(d_min) / (N*D)
// ---------------------------------------------------------------------------
__global__ void vq_finish_kernel(float* __restrict__ out_loss, int nb, long long nd) {
  int t = threadIdx.x;
  double v = (t < nb) ? (double)g_partial[t] : 0.0;
  #pragma unroll
  for (int o = 16; o > 0; o >>= 1) v += __shfl_xor_sync(0xFFFFFFFFu, v, o);
  __shared__ double red[32];
  if ((t & 31) == 0) red[t >> 5] = v;
  __syncthreads();
  if (t < 32) {
    double w = (t < (int)(blockDim.x >> 5)) ? red[t] : 0.0;
    #pragma unroll
    for (int o = 16; o > 0; o >>= 1) w += __shfl_xor_sync(0xFFFFFFFFu, w, o);
    if (t == 0) out_loss[0] = (float)(1.25 * w / (double)nd);
  }
}

// ---------------------------------------------------------------------------
extern "C" void kernel_launch(void* const* d_in, const int* in_sizes, int n_in,
                              void* d_out, int out_size) {
  const float* z   = (const float*)d_in[0];   // [N,1,64] fp32
  const float* emb = (const float*)d_in[1];   // [1024,64] fp32
  float* out = (float*)d_out;

  const int N = in_sizes[0] / D;              // 131072
  float* out_zq   = out;                      // [N*D]
  float* out_idx  = out + (size_t)N * D;      // [N] (indices as float)
  float* out_loss = out_idx + N;              // [1]

  vq_prep_kernel<<<(KCODES + 127) / 128, 128>>>(emb);

  cudaFuncSetAttribute(vq_main_kernel,
                       cudaFuncAttributeMaxDynamicSharedMemorySize, SM_TOTAL);
  vq_main_kernel<<<N / TM, THREADS, SM_TOTAL>>>(z, emb, out_zq, out_idx);

  vq_fix_kernel<<<128, 256>>>(z, emb, out_zq, out_idx);

  vq_finish_kernel<<<1, 1024>>>(out_loss, N / TM, (long long)N * D);
}

// round 14
// speedup vs baseline: 13.1626x; 1.0609x over previous
#include <cuda_runtime.h>
#include <cfloat>

// Problem constants (fixed by the dataset)
#define D        64
#define KCODES   1024
#define TM       128          // rows per CTA
#define TK       128          // codes per chunk
#define NCHUNK   (KCODES / TK)
#define NTILE    (TK / 8)     // 8-code n-tiles per chunk
#define THREADS  256
#define NROWS_MAX 131072

typedef unsigned int u32;
typedef unsigned long long u64;

// Scratch (__device__ globals, allocation-free rule)
__device__ float g_en[KCODES];                        // ||e_k||^2, reference order
__device__ __align__(16) float g_ehi[KCODES * D];     // E hi (tf32 values), fragment-packed
__device__ float g_partial[1024];
__device__ int   g_risky_count;
__device__ int   g_risky[NROWS_MAX];

// SMEM layout (bytes): two E-chunk buffers (double-buffered via cp.async)
#define SM_EA     0            // 32 KB buffer A
#define SM_EB     32768        // 32 KB buffer B (aliased by z staging at start)
#define SM_IDX    65536        // 128 ints
#define SM_RED    66048        // 8 floats
#define SM_TOTAL  66176

__device__ __forceinline__ u32 to_tf32(float v) {
  u32 r; asm("cvt.rna.tf32.f32 %0, %1;" : "=r"(r) : "f"(v)); return r;
}
__device__ __forceinline__ void cp_async16(u32 saddr, const void* gptr) {
  asm volatile("cp.async.cg.shared.global [%0], [%1], 16;"
               :: "r"(saddr), "l"(gptr) : "memory");
}
#define CP_COMMIT() asm volatile("cp.async.commit_group;" ::: "memory")
#define CP_WAIT(n)  asm volatile("cp.async.wait_group %0;" :: "n"(n) : "memory")

// packed f32x2 helpers (fma.rn.f32x2 verified working on this harness in R5)
__device__ __forceinline__ u64 pack2f(float a, float b) {
  u64 r; asm("mov.b64 %0, {%1, %2};" : "=l"(r) : "f"(a), "f"(b)); return r;
}
__device__ __forceinline__ void unpack2f(u64 v, float& a, float& b) {
  asm("mov.b64 {%0, %1}, %2;" : "=f"(a), "=f"(b) : "l"(v));
}
__device__ __forceinline__ u64 fmaf2(u64 a, u64 b, u64 c) {
  u64 r; asm("fma.rn.f32x2 %0, %1, %2, %3;" : "=l"(r) : "l"(a), "l"(b), "l"(c));
  return r;
}

__device__ __forceinline__ void mma_tf32(float& d0, float& d1, float& d2, float& d3,
                                         u32 a0, u32 a1, u32 a2, u32 a3,
                                         u32 b0, u32 b1) {
  asm volatile(
    "mma.sync.aligned.m16n8k8.row.col.f32.tf32.tf32.f32 "
    "{%0,%1,%2,%3}, {%4,%5,%6,%7}, {%8,%9}, {%0,%1,%2,%3};"
    : "+f"(d0), "+f"(d1), "+f"(d2), "+f"(d3)
    : "r"(a0), "r"(a1), "r"(a2), "r"(a3), "r"(b0), "r"(b1));
}

// Reference-order squared-norm (verified): 4 lanes, (S0+S2)+(S1+S3)
__device__ __forceinline__ float ref_sqnorm_seq(const float* base) {
  float S[4] = {0.f, 0.f, 0.f, 0.f};
  #pragma unroll
  for (int i = 0; i < D / 4; i++)
    #pragma unroll
    for (int j = 0; j < 4; j++) {
      float v = base[4 * i + j];
      S[j] = __fadd_rn(S[j], __fmul_rn(v, v));
    }
  return __fadd_rn(__fadd_rn(S[0], S[2]), __fadd_rn(S[1], S[3]));
}

// ---------------------------------------------------------------------------
// Kernel 0: prep — en (reference order) + E-hi fragment packing + counter reset
// ---------------------------------------------------------------------------
__global__ void vq_prep_kernel(const float* __restrict__ emb) {
  int k = blockIdx.x * blockDim.x + threadIdx.x;
  if (k == 0) g_risky_count = 0;
  if (k >= KCODES) return;
  const int chunk = k >> 7, local = k & 127;
  const int tt = local >> 3, np = local & 7;
  const float* e = emb + (size_t)k * D;

  g_en[k] = ref_sqnorm_seq(e);

  float ehi[D];
  #pragma unroll
  for (int i = 0; i < D; i++)
    ehi[i] = __uint_as_float(to_tf32(e[i]));

  // fragment pack: float2 = { E[tt*8 + l/4][8ks + l%4], E[same][8ks + l%4 + 4] }
  #pragma unroll
  for (int ks = 0; ks < 8; ks++)
    #pragma unroll
    for (int kk = 0; kk < 4; kk++) {
      int l = np * 4 + kk;
      size_t off = (size_t)chunk * 8192 + (size_t)((tt * 8 + ks) * 32 + l) * 2;
      *(float2*)(g_ehi + off) = make_float2(ehi[8 * ks + kk], ehi[8 * ks + kk + 4]);
    }
}

// ---------------------------------------------------------------------------
// Kernel 1: single-pass tf32 mma scores; FMNMX-based top-2 epilogue
// ---------------------------------------------------------------------------
__global__ void __launch_bounds__(THREADS, 2)
vq_main_kernel(const float* __restrict__ z, const float* __restrict__ emb,
               float* __restrict__ out_zq, float* __restrict__ out_idx) {
  extern __shared__ __align__(16) char smem[];
  int*    sidx  = (int*)(smem + SM_IDX);
  float*  sred  = (float*)(smem + SM_RED);
  float*  zstage = (float*)(smem + SM_EB);   // alias buf B: consumed pre-loop

  const int t = threadIdx.x;
  const int w = t >> 5, lane = t & 31;
  const int g = lane >> 2, m = lane & 3;
  const int lr0 = w * 16 + g, lr1 = lr0 + 8;  // this thread's two rows (local)
  const size_t rowBase = (size_t)blockIdx.x * TM;

  char* cur = smem + SM_EA;
  char* oth = smem + SM_EB;

  // --- prologue: async-load chunk 0 into buffer A (overlaps z processing) ---
  {
    u32 sa = (u32)__cvta_generic_to_shared(cur) + t * 16;
    const float4* gp = (const float4*)g_ehi + t;
    #pragma unroll
    for (int i = 0; i < 8; i++)
      cp_async16(sa + i * THREADS * 16, gp + i * THREADS);
    CP_COMMIT();
  }

  // --- stage z tile (raw row-major [128][64]) into buffer B ---
  {
    const float4* src = (const float4*)(z + rowBase * D);
    float4* dst = (float4*)zstage;
    #pragma unroll
    for (int i = 0; i < 8; i++) dst[t + i * THREADS] = src[t + i * THREADS];
  }
  __syncthreads();

  // --- A-hi fragments (persistent) + reference-order zn via quad shfl ---
  u32 ah0[8], ah1[8], ah2[8], ah3[8];
  float zn0, zn1;
  {
    const float* zr0 = zstage + lr0 * D;
    const float* zr1 = zstage + lr1 * D;
    float S0 = 0.f, S1 = 0.f;          // S_m partial for rows r0, r1
    #pragma unroll
    for (int ks = 0; ks < 8; ks++) {
      float v00 = zr0[8 * ks + m], v01 = zr0[8 * ks + m + 4];
      float v10 = zr1[8 * ks + m], v11 = zr1[8 * ks + m + 4];
      S0 = __fadd_rn(S0, __fmul_rn(v00, v00));
      S0 = __fadd_rn(S0, __fmul_rn(v01, v01));
      S1 = __fadd_rn(S1, __fmul_rn(v10, v10));
      S1 = __fadd_rn(S1, __fmul_rn(v11, v11));
      ah0[ks] = to_tf32(v00); ah2[ks] = to_tf32(v01);
      ah1[ks] = to_tf32(v10); ah3[ks] = to_tf32(v11);
    }
    // zn = (S0+S2)+(S1+S3): quad butterfly, commutative fadd keeps bits equal
    float T0 = __fadd_rn(S0, __shfl_xor_sync(0xFFFFFFFFu, S0, 2));
    zn0 = __fadd_rn(T0, __shfl_xor_sync(0xFFFFFFFFu, T0, 1));
    float T1 = __fadd_rn(S1, __shfl_xor_sync(0xFFFFFFFFu, S1, 2));
    zn1 = __fadd_rn(T1, __shfl_xor_sync(0xFFFFFFFFu, T1, 1));
  }
  __syncthreads();   // z staging fully consumed; buffer B free for prefetch

  const u64 zn0p = pack2f(zn0, zn0);
  const u64 zn1p = pack2f(zn1, zn1);
  const u64 ONE2 = pack2f(1.0f, 1.0f);
  const u64 NEG2 = pack2f(-2.0f, -2.0f);

  float min0v = FLT_MAX, min1v = FLT_MAX;   // best quantized d
  float min0s = FLT_MAX, min1s = FLT_MAX;   // second-best (value only)
  int   min0i = 0,       min1i = 0;

  for (int ch = 0; ch < NCHUNK; ch++) {
    // prefetch next chunk into the other buffer; wait for current chunk
    if (ch + 1 < NCHUNK) {
      u32 sa = (u32)__cvta_generic_to_shared(oth) + t * 16;
      const float4* gp = (const float4*)(g_ehi + (size_t)(ch + 1) * 8192) + t;
      #pragma unroll
      for (int i = 0; i < 8; i++)
        cp_async16(sa + i * THREADS * 16, gp + i * THREADS);
      CP_COMMIT();
      CP_WAIT(1);
    } else {
      CP_WAIT(0);
    }
    __syncthreads();

    const float2* e_hi = (const float2*)cur;
    #pragma unroll
    for (int tt = 0; tt < NTILE; tt++) {
      // B-hi fragments prefetched into regs
      u32 bh0[8], bh1[8];
      #pragma unroll
      for (int ks = 0; ks < 8; ks++) {
        float2 b = e_hi[(tt * 8 + ks) * 32 + lane];
        bh0[ks] = __float_as_uint(b.x);
        bh1[ks] = __float_as_uint(b.y);
      }
      // single pass: zh . eh
      float d0 = 0.f, d1 = 0.f, d2 = 0.f, d3 = 0.f;
      #pragma unroll
      for (int ks = 0; ks < 8; ks++)
        mma_tf32(d0, d1, d2, d3, ah0[ks], ah1[ks], ah2[ks], ah3[ks],
                 bh0[ks], bh1[ks]);

      // epilogue (bit-identical to verified formula):
      //   dv = fl(fl(zn+en) - 2*dot)   [2*dot exact => fused fma legal]
      const int cb = ch * TK + tt * 8 + 2 * m;
      float2 en2 = __ldg((const float2*)(g_en + cb));
      u64 en2p = pack2f(en2.x, en2.y);
      u64 s0 = fmaf2(zn0p, ONE2, en2p);        // {fl(zn0+en.x), fl(zn0+en.y)}
      u64 s1 = fmaf2(zn1p, ONE2, en2p);
      float dv0, dv1, dv2, dv3;
      unpack2f(fmaf2(pack2f(d0, d1), NEG2, s0), dv0, dv1);
      unpack2f(fmaf2(pack2f(d2, d3), NEG2, s1), dv2, dv3);

      // row 0: FMNMX-chain top-2 (value), predicate only for best index
      {
        float lo = fminf(dv0, dv1), hi = fmaxf(dv0, dv1);
        int ip = (dv0 <= dv1) ? cb : cb + 1;          // pair tie -> lower code
        if (lo < min0v) min0i = ip;                   // strict < keeps earliest
        min0s = fminf(fmaxf(min0v, lo), fminf(min0s, hi));
        min0v = fminf(min0v, lo);
      }
      // row 1
      {
        float lo = fminf(dv2, dv3), hi = fmaxf(dv2, dv3);
        int ip = (dv2 <= dv3) ? cb : cb + 1;
        if (lo < min1v) min1i = ip;
        min1s = fminf(fmaxf(min1v, lo), fminf(min1s, hi));
        min1v = fminf(min1v, lo);
      }
    }
    __syncthreads();   // all tiles consumed before this buffer is refilled
    char* tmp = cur; cur = oth; oth = tmp;
  }

  // --- cross-lane top-2 argmin within each quad (tie -> lowest index) ---
  #pragma unroll
  for (int off = 1; off <= 2; off <<= 1) {
    float ov = __shfl_xor_sync(0xFFFFFFFFu, min0v, off);
    int   oi = __shfl_xor_sync(0xFFFFFFFFu, min0i, off);
    float os = __shfl_xor_sync(0xFFFFFFFFu, min0s, off);
    if (ov < min0v || (ov == min0v && oi < min0i)) {
      min0s = fminf(min0v, os); min0v = ov; min0i = oi;
    } else min0s = fminf(min0s, ov);
    ov = __shfl_xor_sync(0xFFFFFFFFu, min1v, off);
    oi = __shfl_xor_sync(0xFFFFFFFFu, min1i, off);
    os = __shfl_xor_sync(0xFFFFFFFFu, min1s, off);
    if (ov < min1v || (ov == min1v && oi < min1i)) {
      min1s = fminf(min1v, os); min1v = ov; min1i = oi;
    } else min1s = fminf(min1s, ov);
  }

  float contrib = 0.f;
  if (m == 0) {
    sidx[lr0] = min0i; sidx[lr1] = min1i;
    out_idx[rowBase + lr0] = (float)min0i;
    out_idx[rowBase + lr1] = (float)min1i;
    contrib = min0v + min1v;   // quantized d_min values (verified semantics)
    // risky rows: top-2 gap within 4e-5 ABSOLUTE (~5.3 grid steps = 7.6 sigma
    // of the single-pass d-difference error) -> exact rescore later
    if (min0s - min0v <= 4e-5f) {
      int p = atomicAdd(&g_risky_count, 1);
      g_risky[p] = (int)(rowBase + lr0);
    }
    if (min1s - min1v <= 4e-5f) {
      int p = atomicAdd(&g_risky_count, 1);
      g_risky[p] = (int)(rowBase + lr1);
    }
  }
  // warp sum of loss contributions
  #pragma unroll
  for (int o = 16; o > 0; o >>= 1) contrib += __shfl_xor_sync(0xFFFFFFFFu, contrib, o);
  if (lane == 0) sred[w] = contrib;
  __syncthreads();
  if (t == 0) {
    float tot = 0.f;
    #pragma unroll
    for (int i = 0; i < 8; i++) tot += sred[i];
    g_partial[blockIdx.x] = tot;
  }

  // coalesced z_q gather: 16 float4 lanes per row
  for (int j = t; j < TM * (D / 4); j += THREADS) {
    int r2 = j >> 4, p = j & 15;
    ((float4*)(out_zq + (rowBase + r2) * D))[p] =
        ((const float4*)(emb + (size_t)sidx[r2] * D))[p];
  }
}

// ---------------------------------------------------------------------------
// Kernel 1b: exact rescore of risky rows — coalesced (validated round 13).
// ---------------------------------------------------------------------------
__global__ void __launch_bounds__(256, 4)
vq_fix_kernel(const float* __restrict__ z, const float* __restrict__ emb,
              float* __restrict__ out_zq, float* __restrict__ out_idx) {
  __shared__ float zrow[8][D];
  const int wl = threadIdx.x >> 5, lane = threadIdx.x & 31;
  const int q = lane >> 2, m = lane & 3;
  const int wg = blockIdx.x * 8 + wl;
  const int nw = gridDim.x * 8;
  const int cnt = g_risky_count;

  for (int i = wg; i < cnt; i += nw) {
    const int row = g_risky[i];
    ((float2*)zrow[wl])[lane] = ((const float2*)(z + (size_t)row * D))[lane];
    __syncwarp();

    const float zn = ref_sqnorm_seq(zrow[wl]);

    float zf[16];
    #pragma unroll
    for (int d2 = 0; d2 < 16; d2++) zf[d2] = zrow[wl][m * 16 + d2];

    float bestv = FLT_MAX; int besti = 0;
    for (int c0 = 0; c0 < KCODES; c0 += 8) {
      const int code = c0 + q;
      const float4* ep = (const float4*)(emb + (size_t)code * D + m * 16);
      float p = 0.f;
      #pragma unroll
      for (int v4 = 0; v4 < 4; v4++) {
        float4 ev = __ldg(ep + v4);
        p = __fmaf_rn(zf[v4 * 4 + 0], ev.x, p);
        p = __fmaf_rn(zf[v4 * 4 + 1], ev.y, p);
        p = __fmaf_rn(zf[v4 * 4 + 2], ev.z, p);
        p = __fmaf_rn(zf[v4 * 4 + 3], ev.w, p);
      }
      p += __shfl_xor_sync(0xFFFFFFFFu, p, 1);
      p += __shfl_xor_sync(0xFFFFFFFFu, p, 2);
      float dv = __fsub_rn(__fadd_rn(zn, __ldg(&g_en[code])), __fadd_rn(p, p));
      if (dv < bestv) { bestv = dv; besti = code; }  // codes ascending per quad
    }
    #pragma unroll
    for (int off = 4; off <= 16; off <<= 1) {
      float ov = __shfl_xor_sync(0xFFFFFFFFu, bestv, off);
      int   oi = __shfl_xor_sync(0xFFFFFFFFu, besti, off);
      if (ov < bestv || (ov == bestv && oi < besti)) { bestv = ov; besti = oi; }
    }
    if (lane == 0) out_idx[row] = (float)besti;
    if (lane < 16)
      ((float4*)(out_zq + (size_t)row * D))[lane] =
          ((const float4*)(emb + (size_t)besti * D))[lane];
    __syncwarp();
  }
}

// ---------------------------------------------------------------------------
// Kernel 2: deterministic loss reduction (double accumulation)
// ---------------------------------------------------------------------------
__global__ void vq_finish_kernel(float* __restrict__ out_loss, int nb, long long nd) {
  int t = threadIdx.x;
  double v = (t < nb) ? (double)g_partial[t] : 0.0;
  #pragma unroll
  for (int o = 16; o > 0; o >>= 1) v += __shfl_xor_sync(0xFFFFFFFFu, v, o);
  __shared__ double red[32];
  if ((t & 31) == 0) red[t >> 5] = v;
  __syncthreads();
  if (t < 32) {
    double w = (t < (int)(blockDim.x >> 5)) ? red[t] : 0.0;
    #pragma unroll
    for (int o = 16; o > 0; o >>= 1) w += __shfl_xor_sync(0xFFFFFFFFu, w, o);
    if (t == 0) out_loss[0] = (float)(1.25 * w / (double)nd);
  }
}

// ---------------------------------------------------------------------------
extern "C" void kernel_launch(void* const* d_in, const int* in_sizes, int n_in,
                              void* d_out, int out_size) {
  const float* z   = (const float*)d_in[0];   // [N,1,64] fp32
  const float* emb = (const float*)d_in[1];   // [1024,64] fp32
  float* out = (float*)d_out;

  const int N = in_sizes[0] / D;              // 131072
  float* out_zq   = out;                      // [N*D]
  float* out_idx  = out + (size_t)N * D;      // [N] (indices as float)
  float* out_loss = out_idx + N;              // [1]

  vq_prep_kernel<<<(KCODES + 127) / 128, 128>>>(emb);

  cudaFuncSetAttribute(vq_main_kernel,
                       cudaFuncAttributeMaxDynamicSharedMemorySize, SM_TOTAL);
  vq_main_kernel<<<N / TM, THREADS, SM_TOTAL>>>(z, emb, out_zq, out_idx);

  vq_fix_kernel<<<128, 256>>>(z, emb, out_zq, out_idx);

  vq_finish_kernel<<<1, 1024>>>(out_loss, N / TM, (long long)N * D);
}

// round 15
// speedup vs baseline: 15.0383x; 1.1425x over previous
#include <cuda_runtime.h>
#include <cuda_fp16.h>
#include <cfloat>

// Problem constants (fixed by the dataset)
#define D        64
#define KCODES   1024
#define TM       128          // rows per CTA
#define TK       128          // codes per chunk
#define NCHUNK   (KCODES / TK)
#define NTILE    (TK / 8)     // 8-code n-tiles per chunk
#define THREADS  256
#define NROWS_MAX 131072

typedef unsigned int u32;
typedef unsigned long long u64;

// E scale: e' = e * 2^10 (exact), undone via dot * -2^-9 == -2*dot (exact pow2)
#define ESCALE   1024.0f
#define NEGINV   (-1.0f / 512.0f)

// Scratch (__device__ globals, allocation-free rule)
__device__ float g_en[KCODES];                      // ||e_k||^2, reference order
__device__ __align__(16) u32 g_eh[KCODES * D / 2];  // E fp16x2 (scaled), frag-packed
__device__ float g_partial[1024];
__device__ int   g_risky_count;
__device__ int   g_risky[NROWS_MAX];

// SMEM layout (bytes)
#define SM_EA     0            // 16 KB chunk buffer A
#define SM_EB     16384        // 16 KB chunk buffer B
#define SM_ZST    32768        // 32 KB z staging
#define SM_IDX    65536        // 128 ints
#define SM_RED    66048        // 8 floats
#define SM_TOTAL  66176

__device__ __forceinline__ void cp_async16(u32 saddr, const void* gptr) {
  asm volatile("cp.async.cg.shared.global [%0], [%1], 16;"
               :: "r"(saddr), "l"(gptr) : "memory");
}
#define CP_COMMIT() asm volatile("cp.async.commit_group;" ::: "memory")
#define CP_WAIT(n)  asm volatile("cp.async.wait_group %0;" :: "n"(n) : "memory")

// packed f32x2 helpers (verified on this harness)
__device__ __forceinline__ u64 pack2f(float a, float b) {
  u64 r; asm("mov.b64 %0, {%1, %2};" : "=l"(r) : "f"(a), "f"(b)); return r;
}
__device__ __forceinline__ void unpack2f(u64 v, float& a, float& b) {
  asm("mov.b64 {%0, %1}, %2;" : "=f"(a), "=f"(b) : "l"(v));
}
__device__ __forceinline__ u64 fmaf2(u64 a, u64 b, u64 c) {
  u64 r; asm("fma.rn.f32x2 %0, %1, %2, %3;" : "=l"(r) : "l"(a), "l"(b), "l"(c));
  return r;
}
// pack two f32 -> f16x2 register (lo = first element)
__device__ __forceinline__ u32 h2pack(float lo, float hi) {
  u32 r; asm("cvt.rn.f16x2.f32 %0, %1, %2;" : "=r"(r) : "f"(hi), "f"(lo));
  return r;
}

__device__ __forceinline__ void mma_f16(float& d0, float& d1, float& d2, float& d3,
                                        u32 a0, u32 a1, u32 a2, u32 a3,
                                        u32 b0, u32 b1) {
  asm volatile(
    "mma.sync.aligned.m16n8k16.row.col.f32.f16.f16.f32 "
    "{%0,%1,%2,%3}, {%4,%5,%6,%7}, {%8,%9}, {%0,%1,%2,%3};"
    : "+f"(d0), "+f"(d1), "+f"(d2), "+f"(d3)
    : "r"(a0), "r"(a1), "r"(a2), "r"(a3), "r"(b0), "r"(b1));
}

// Reference-order squared-norm (verified): 4 lanes, (S0+S2)+(S1+S3)
__device__ __forceinline__ float ref_sqnorm_seq(const float* base) {
  float S[4] = {0.f, 0.f, 0.f, 0.f};
  #pragma unroll
  for (int i = 0; i < D / 4; i++)
    #pragma unroll
    for (int j = 0; j < 4; j++) {
      float v = base[4 * i + j];
      S[j] = __fadd_rn(S[j], __fmul_rn(v, v));
    }
  return __fadd_rn(__fadd_rn(S[0], S[2]), __fadd_rn(S[1], S[3]));
}

// ---------------------------------------------------------------------------
// Kernel 0: prep — en + scaled-fp16 E fragment packing + counter reset
// Layout: lane l = 4*g + m holds code tt*8+g; per kstep s:
//   b0 = {e'[16s+2m], e'[16s+2m+1]}, b1 = {e'[16s+2m+8], e'[16s+2m+9]}
//   at u32 offset chunk*4096 + ((tt*4+s)*32 + l)*2
// ---------------------------------------------------------------------------
__global__ void vq_prep_kernel(const float* __restrict__ emb) {
  int k = blockIdx.x * blockDim.x + threadIdx.x;
  if (k == 0) g_risky_count = 0;
  if (k >= KCODES) return;
  const int chunk = k >> 7, local = k & 127;
  const int tt = local >> 3, np = local & 7;
  const float* e = emb + (size_t)k * D;

  g_en[k] = ref_sqnorm_seq(e);

  #pragma unroll
  for (int s = 0; s < 4; s++)
    #pragma unroll
    for (int m = 0; m < 4; m++) {
      u32 b0 = h2pack(e[16 * s + 2 * m] * ESCALE,     e[16 * s + 2 * m + 1] * ESCALE);
      u32 b1 = h2pack(e[16 * s + 2 * m + 8] * ESCALE, e[16 * s + 2 * m + 9] * ESCALE);
      u32 off = (u32)chunk * 4096u + (u32)((tt * 4 + s) * 32 + np * 4 + m) * 2u;
      g_eh[off] = b0;
      g_eh[off + 1] = b1;
    }
}

// ---------------------------------------------------------------------------
// Kernel 1: single-pass fp16 m16n8k16 mma scores; FMNMX top-2 epilogue
// ---------------------------------------------------------------------------
__global__ void __launch_bounds__(THREADS, 2)
vq_main_kernel(const float* __restrict__ z, const float* __restrict__ emb,
               float* __restrict__ out_zq, float* __restrict__ out_idx) {
  extern __shared__ __align__(16) char smem[];
  int*    sidx  = (int*)(smem + SM_IDX);
  float*  sred  = (float*)(smem + SM_RED);
  float*  zstage = (float*)(smem + SM_ZST);

  const int t = threadIdx.x;
  const int w = t >> 5, lane = t & 31;
  const int g = lane >> 2, m = lane & 3;
  const int lr0 = w * 16 + g, lr1 = lr0 + 8;  // this thread's two rows (local)
  const size_t rowBase = (size_t)blockIdx.x * TM;

  char* cur = smem + SM_EA;
  char* oth = smem + SM_EB;

  // --- prologue: async-load chunk 0 (16 KB) into buffer A ---
  {
    u32 sa = (u32)__cvta_generic_to_shared(cur) + t * 16;
    const float4* gp = (const float4*)g_eh + t;
    #pragma unroll
    for (int i = 0; i < 4; i++)
      cp_async16(sa + i * THREADS * 16, gp + i * THREADS);
    CP_COMMIT();
  }

  // --- stage z tile (raw row-major [128][64]) ---
  {
    const float4* src = (const float4*)(z + rowBase * D);
    float4* dst = (float4*)zstage;
    #pragma unroll
    for (int i = 0; i < 8; i++) dst[t + i * THREADS] = src[t + i * THREADS];
  }
  __syncthreads();

  // --- reference-order zn (verified read pattern + quad butterfly) ---
  float zn0, zn1;
  {
    const float* zr0 = zstage + lr0 * D;
    const float* zr1 = zstage + lr1 * D;
    float S0 = 0.f, S1 = 0.f;
    #pragma unroll
    for (int ks = 0; ks < 8; ks++) {
      float v00 = zr0[8 * ks + m], v01 = zr0[8 * ks + m + 4];
      float v10 = zr1[8 * ks + m], v11 = zr1[8 * ks + m + 4];
      S0 = __fadd_rn(S0, __fmul_rn(v00, v00));
      S0 = __fadd_rn(S0, __fmul_rn(v01, v01));
      S1 = __fadd_rn(S1, __fmul_rn(v10, v10));
      S1 = __fadd_rn(S1, __fmul_rn(v11, v11));
    }
    float T0 = __fadd_rn(S0, __shfl_xor_sync(0xFFFFFFFFu, S0, 2));
    zn0 = __fadd_rn(T0, __shfl_xor_sync(0xFFFFFFFFu, T0, 1));
    float T1 = __fadd_rn(S1, __shfl_xor_sync(0xFFFFFFFFu, S1, 2));
    zn1 = __fadd_rn(T1, __shfl_xor_sync(0xFFFFFFFFu, T1, 1));
  }

  // --- fp16 A-fragments: ah[s] = {a0,a1,a2,a3} for kstep s ---
  u32 ah[4][4];
  {
    const float* zr0 = zstage + lr0 * D;
    const float* zr1 = zstage + lr1 * D;
    #pragma unroll
    for (int s = 0; s < 4; s++) {
      float2 p00 = *(const float2*)&zr0[16 * s + 2 * m];
      float2 p01 = *(const float2*)&zr0[16 * s + 2 * m + 8];
      float2 p10 = *(const float2*)&zr1[16 * s + 2 * m];
      float2 p11 = *(const float2*)&zr1[16 * s + 2 * m + 8];
      ah[s][0] = h2pack(p00.x, p00.y);
      ah[s][1] = h2pack(p10.x, p10.y);
      ah[s][2] = h2pack(p01.x, p01.y);
      ah[s][3] = h2pack(p11.x, p11.y);
    }
  }
  __syncthreads();

  const u64 zn0p = pack2f(zn0, zn0);
  const u64 zn1p = pack2f(zn1, zn1);
  const u64 ONE2 = pack2f(1.0f, 1.0f);
  const u64 NEG2 = pack2f(NEGINV, NEGINV);   // dot' * -2^-9 == -2*dot (exact)

  float min0v = FLT_MAX, min1v = FLT_MAX;   // best quantized d
  float min0s = FLT_MAX, min1s = FLT_MAX;   // second-best (value only)
  int   min0i = 0,       min1i = 0;

  for (int ch = 0; ch < NCHUNK; ch++) {
    // prefetch next chunk (16 KB) into the other buffer; wait for current
    if (ch + 1 < NCHUNK) {
      u32 sa = (u32)__cvta_generic_to_shared(oth) + t * 16;
      const float4* gp = (const float4*)(g_eh + (size_t)(ch + 1) * 4096) + t;
      #pragma unroll
      for (int i = 0; i < 4; i++)
        cp_async16(sa + i * THREADS * 16, gp + i * THREADS);
      CP_COMMIT();
      CP_WAIT(1);
    } else {
      CP_WAIT(0);
    }
    __syncthreads();

    const uint2* e_h = (const uint2*)cur;
    #pragma unroll
    for (int tt = 0; tt < NTILE; tt++) {
      // B fragments (4 ksteps), conflict-free LDS.64
      uint2 bf[4];
      #pragma unroll
      for (int s = 0; s < 4; s++)
        bf[s] = e_h[(tt * 4 + s) * 32 + lane];

      float d0 = 0.f, d1 = 0.f, d2 = 0.f, d3 = 0.f;
      #pragma unroll
      for (int s = 0; s < 4; s++)
        mma_f16(d0, d1, d2, d3, ah[s][0], ah[s][1], ah[s][2], ah[s][3],
                bf[s].x, bf[s].y);

      // epilogue: dv = fl(fl(zn+en) + dot'*(-2^-9))  [== verified formula]
      const int cb = ch * TK + tt * 8 + 2 * m;
      float2 en2 = __ldg((const float2*)(g_en + cb));
      u64 en2p = pack2f(en2.x, en2.y);
      u64 s0 = fmaf2(zn0p, ONE2, en2p);
      u64 s1 = fmaf2(zn1p, ONE2, en2p);
      float dv0, dv1, dv2, dv3;
      unpack2f(fmaf2(pack2f(d0, d1), NEG2, s0), dv0, dv1);
      unpack2f(fmaf2(pack2f(d2, d3), NEG2, s1), dv2, dv3);

      {
        float lo = fminf(dv0, dv1), hi = fmaxf(dv0, dv1);
        int ip = (dv0 <= dv1) ? cb : cb + 1;          // pair tie -> lower code
        if (lo < min0v) min0i = ip;                   // strict < keeps earliest
        min0s = fminf(fmaxf(min0v, lo), fminf(min0s, hi));
        min0v = fminf(min0v, lo);
      }
      {
        float lo = fminf(dv2, dv3), hi = fmaxf(dv2, dv3);
        int ip = (dv2 <= dv3) ? cb : cb + 1;
        if (lo < min1v) min1i = ip;
        min1s = fminf(fmaxf(min1v, lo), fminf(min1s, hi));
        min1v = fminf(min1v, lo);
      }
    }
    __syncthreads();   // all tiles consumed before this buffer is refilled
    char* tmp = cur; cur = oth; oth = tmp;
  }

  // --- cross-lane top-2 argmin within each quad (tie -> lowest index) ---
  #pragma unroll
  for (int off = 1; off <= 2; off <<= 1) {
    float ov = __shfl_xor_sync(0xFFFFFFFFu, min0v, off);
    int   oi = __shfl_xor_sync(0xFFFFFFFFu, min0i, off);
    float os = __shfl_xor_sync(0xFFFFFFFFu, min0s, off);
    if (ov < min0v || (ov == min0v && oi < min0i)) {
      min0s = fminf(min0v, os); min0v = ov; min0i = oi;
    } else min0s = fminf(min0s, ov);
    ov = __shfl_xor_sync(0xFFFFFFFFu, min1v, off);
    oi = __shfl_xor_sync(0xFFFFFFFFu, min1i, off);
    os = __shfl_xor_sync(0xFFFFFFFFu, min1s, off);
    if (ov < min1v || (ov == min1v && oi < min1i)) {
      min1s = fminf(min1v, os); min1v = ov; min1i = oi;
    } else min1s = fminf(min1s, ov);
  }

  float contrib = 0.f;
  if (m == 0) {
    sidx[lr0] = min0i; sidx[lr1] = min1i;
    out_idx[rowBase + lr0] = (float)min0i;
    out_idx[rowBase + lr1] = (float)min1i;
    contrib = min0v + min1v;   // quantized d_min values
    // risky rows: top-2 gap within 4e-5 ABSOLUTE (~9 sigma of fp16-pass
    // d-difference error) -> exact rescore later
    if (min0s - min0v <= 4e-5f) {
      int p = atomicAdd(&g_risky_count, 1);
      g_risky[p] = (int)(rowBase + lr0);
    }
    if (min1s - min1v <= 4e-5f) {
      int p = atomicAdd(&g_risky_count, 1);
      g_risky[p] = (int)(rowBase + lr1);
    }
  }
  // warp sum of loss contributions
  #pragma unroll
  for (int o = 16; o > 0; o >>= 1) contrib += __shfl_xor_sync(0xFFFFFFFFu, contrib, o);
  if (lane == 0) sred[w] = contrib;
  __syncthreads();
  if (t == 0) {
    float tot = 0.f;
    #pragma unroll
    for (int i = 0; i < 8; i++) tot += sred[i];
    g_partial[blockIdx.x] = tot;
  }

  // coalesced z_q gather: 16 float4 lanes per row
  for (int j = t; j < TM * (D / 4); j += THREADS) {
    int r2 = j >> 4, p = j & 15;
    ((float4*)(out_zq + (rowBase + r2) * D))[p] =
        ((const float4*)(emb + (size_t)sidx[r2] * D))[p];
  }
}

// ---------------------------------------------------------------------------
// Kernel 1b: exact rescore of risky rows — coalesced (validated round 13).
// ---------------------------------------------------------------------------
__global__ void __launch_bounds__(256, 4)
vq_fix_kernel(const float* __restrict__ z, const float* __restrict__ emb,
              float* __restrict__ out_zq, float* __restrict__ out_idx) {
  __shared__ float zrow[8][D];
  const int wl = threadIdx.x >> 5, lane = threadIdx.x & 31;
  const int q = lane >> 2, m = lane & 3;
  const int wg = blockIdx.x * 8 + wl;
  const int nw = gridDim.x * 8;
  const int cnt = g_risky_count;

  for (int i = wg; i < cnt; i += nw) {
    const int row = g_risky[i];
    ((float2*)zrow[wl])[lane] = ((const float2*)(z + (size_t)row * D))[lane];
    __syncwarp();

    const float zn = ref_sqnorm_seq(zrow[wl]);

    float zf[16];
    #pragma unroll
    for (int d2 = 0; d2 < 16; d2++) zf[d2] = zrow[wl][m * 16 + d2];

    float bestv = FLT_MAX; int besti = 0;
    for (int c0 = 0; c0 < KCODES; c0 += 8) {
      const int code = c0 + q;
      const float4* ep = (const float4*)(emb + (size_t)code * D + m * 16);
      float p = 0.f;
      #pragma unroll
      for (int v4 = 0; v4 < 4; v4++) {
        float4 ev = __ldg(ep + v4);
        p = __fmaf_rn(zf[v4 * 4 + 0], ev.x, p);
        p = __fmaf_rn(zf[v4 * 4 + 1], ev.y, p);
        p = __fmaf_rn(zf[v4 * 4 + 2], ev.z, p);
        p = __fmaf_rn(zf[v4 * 4 + 3], ev.w, p);
      }
      p += __shfl_xor_sync(0xFFFFFFFFu, p, 1);
      p += __shfl_xor_sync(0xFFFFFFFFu, p, 2);
      float dv = __fsub_rn(__fadd_rn(zn, __ldg(&g_en[code])), __fadd_rn(p, p));
      if (dv < bestv) { bestv = dv; besti = code; }  // codes ascending per quad
    }
    #pragma unroll
    for (int off = 4; off <= 16; off <<= 1) {
      float ov = __shfl_xor_sync(0xFFFFFFFFu, bestv, off);
      int   oi = __shfl_xor_sync(0xFFFFFFFFu, besti, off);
      if (ov < bestv || (ov == bestv && oi < besti)) { bestv = ov; besti = oi; }
    }
    if (lane == 0) out_idx[row] = (float)besti;
    if (lane < 16)
      ((float4*)(out_zq + (size_t)row * D))[lane] =
          ((const float4*)(emb + (size_t)besti * D))[lane];
    __syncwarp();
  }
}

// ---------------------------------------------------------------------------
// Kernel 2: deterministic loss reduction (double accumulation)
// ---------------------------------------------------------------------------
__global__ void vq_finish_kernel(float* __restrict__ out_loss, int nb, long long nd) {
  int t = threadIdx.x;
  double v = (t < nb) ? (double)g_partial[t] : 0.0;
  #pragma unroll
  for (int o = 16; o > 0; o >>= 1) v += __shfl_xor_sync(0xFFFFFFFFu, v, o);
  __shared__ double red[32];
  if ((t & 31) == 0) red[t >> 5] = v;
  __syncthreads();
  if (t < 32) {
    double w = (t < (int)(blockDim.x >> 5)) ? red[t] : 0.0;
    #pragma unroll
    for (int o = 16; o > 0; o >>= 1) w += __shfl_xor_sync(0xFFFFFFFFu, w, o);
    if (t == 0) out_loss[0] = (float)(1.25 * w / (double)nd);
  }
}

// ---------------------------------------------------------------------------
extern "C" void kernel_launch(void* const* d_in, const int* in_sizes, int n_in,
                              void* d_out, int out_size) {
  const float* z   = (const float*)d_in[0];   // [N,1,64] fp32
  const float* emb = (const float*)d_in[1];   // [1024,64] fp32
  float* out = (float*)d_out;

  const int N = in_sizes[0] / D;              // 131072
  float* out_zq   = out;                      // [N*D]
  float* out_idx  = out + (size_t)N * D;      // [N] (indices as float)
  float* out_loss = out_idx + N;              // [1]

  vq_prep_kernel<<<(KCODES + 127) / 128, 128>>>(emb);

  cudaFuncSetAttribute(vq_main_kernel,
                       cudaFuncAttributeMaxDynamicSharedMemorySize, SM_TOTAL);
  vq_main_kernel<<<N / TM, THREADS, SM_TOTAL>>>(z, emb, out_zq, out_idx);

  vq_fix_kernel<<<128, 256>>>(z, emb, out_zq, out_idx);

  vq_finish_kernel<<<1, 1024>>>(out_loss, N / TM, (long long)N * D);
}

// round 16
// speedup vs baseline: 15.3113x; 1.0182x over previous
#include <cuda_runtime.h>
#include <cuda_fp16.h>
#include <cfloat>

// Problem constants (fixed by the dataset)
#define D        64
#define KCODES   1024
#define TM       128          // rows per CTA
#define TK       128          // codes per chunk
#define NCHUNK   (KCODES / TK)
#define NTILE    (TK / 8)     // 8-code n-tiles per chunk
#define THREADS  256
#define NROWS_MAX 131072

typedef unsigned int u32;
typedef unsigned long long u64;

// E scale: e' = e * 2^10 (exact), undone via dot * -2^-9 == -2*dot (exact pow2)
#define ESCALE   1024.0f
#define NEGINV   (-1.0f / 512.0f)

// Scratch (__device__ globals, allocation-free rule)
__device__ float g_en[KCODES];                      // ||e_k||^2, reference order
__device__ __align__(16) u32 g_eh[KCODES * D / 2];  // E fp16x2 (scaled), frag-packed
__device__ float g_partial[1024];
__device__ int   g_risky_count;
__device__ int   g_risky[NROWS_MAX];

// SMEM layout (bytes) — no z staging; 3 CTAs/SM
#define SM_EA     0            // 16 KB chunk buffer A
#define SM_EB     16384        // 16 KB chunk buffer B
#define SM_IDX    32768        // 128 ints
#define SM_RED    33280        // 8 floats
#define SM_TOTAL  33408

__device__ __forceinline__ void cp_async16(u32 saddr, const void* gptr) {
  asm volatile("cp.async.cg.shared.global [%0], [%1], 16;"
               :: "r"(saddr), "l"(gptr) : "memory");
}
#define CP_COMMIT() asm volatile("cp.async.commit_group;" ::: "memory")
#define CP_WAIT(n)  asm volatile("cp.async.wait_group %0;" :: "n"(n) : "memory")

// packed f32x2 helpers (verified on this harness)
__device__ __forceinline__ u64 pack2f(float a, float b) {
  u64 r; asm("mov.b64 %0, {%1, %2};" : "=l"(r) : "f"(a), "f"(b)); return r;
}
__device__ __forceinline__ void unpack2f(u64 v, float& a, float& b) {
  asm("mov.b64 {%0, %1}, %2;" : "=f"(a), "=f"(b) : "l"(v));
}
__device__ __forceinline__ u64 fmaf2(u64 a, u64 b, u64 c) {
  u64 r; asm("fma.rn.f32x2 %0, %1, %2, %3;" : "=l"(r) : "l"(a), "l"(b), "l"(c));
  return r;
}
__device__ __forceinline__ u64 addf2(u64 a, u64 b) {
  u64 r; asm("add.rn.f32x2 %0, %1, %2;" : "=l"(r) : "l"(a), "l"(b));
  return r;
}
// pack two f32 -> f16x2 register (lo = first element)
__device__ __forceinline__ u32 h2pack(float lo, float hi) {
  u32 r; asm("cvt.rn.f16x2.f32 %0, %1, %2;" : "=r"(r) : "f"(hi), "f"(lo));
  return r;
}

__device__ __forceinline__ void mma_f16(float& d0, float& d1, float& d2, float& d3,
                                        u32 a0, u32 a1, u32 a2, u32 a3,
                                        u32 b0, u32 b1) {
  asm volatile(
    "mma.sync.aligned.m16n8k16.row.col.f32.f16.f16.f32 "
    "{%0,%1,%2,%3}, {%4,%5,%6,%7}, {%8,%9}, {%0,%1,%2,%3};"
    : "+f"(d0), "+f"(d1), "+f"(d2), "+f"(d3)
    : "r"(a0), "r"(a1), "r"(a2), "r"(a3), "r"(b0), "r"(b1));
}

// Reference-order squared-norm (verified): 4 lanes, (S0+S2)+(S1+S3)
__device__ __forceinline__ float ref_sqnorm_seq(const float* base) {
  float S[4] = {0.f, 0.f, 0.f, 0.f};
  #pragma unroll
  for (int i = 0; i < D / 4; i++)
    #pragma unroll
    for (int j = 0; j < 4; j++) {
      float v = base[4 * i + j];
      S[j] = __fadd_rn(S[j], __fmul_rn(v, v));
    }
  return __fadd_rn(__fadd_rn(S[0], S[2]), __fadd_rn(S[1], S[3]));
}

// ---------------------------------------------------------------------------
// Kernel 0: prep — en + scaled-fp16 E fragment packing + counter reset
// ---------------------------------------------------------------------------
__global__ void vq_prep_kernel(const float* __restrict__ emb) {
  int k = blockIdx.x * blockDim.x + threadIdx.x;
  if (k == 0) g_risky_count = 0;
  if (k >= KCODES) return;
  const int chunk = k >> 7, local = k & 127;
  const int tt = local >> 3, np = local & 7;
  const float* e = emb + (size_t)k * D;

  g_en[k] = ref_sqnorm_seq(e);

  #pragma unroll
  for (int s = 0; s < 4; s++)
    #pragma unroll
    for (int m = 0; m < 4; m++) {
      u32 b0 = h2pack(e[16 * s + 2 * m] * ESCALE,     e[16 * s + 2 * m + 1] * ESCALE);
      u32 b1 = h2pack(e[16 * s + 2 * m + 8] * ESCALE, e[16 * s + 2 * m + 9] * ESCALE);
      u32 off = (u32)chunk * 4096u + (u32)((tt * 4 + s) * 32 + np * 4 + m) * 2u;
      g_eh[off] = b0;
      g_eh[off + 1] = b1;
    }
}

// ---------------------------------------------------------------------------
// Kernel 1: single-pass fp16 m16n8k16 mma scores; 3 CTAs/SM; split accums
// ---------------------------------------------------------------------------
__global__ void __launch_bounds__(THREADS, 3)
vq_main_kernel(const float* __restrict__ z, const float* __restrict__ emb,
               float* __restrict__ out_zq, float* __restrict__ out_idx) {
  extern __shared__ __align__(16) char smem[];
  int*    sidx  = (int*)(smem + SM_IDX);
  float*  sred  = (float*)(smem + SM_RED);

  const int t = threadIdx.x;
  const int w = t >> 5, lane = t & 31;
  const int g = lane >> 2, m = lane & 3;
  const int lr0 = w * 16 + g, lr1 = lr0 + 8;  // this thread's two rows (local)
  const size_t rowBase = (size_t)blockIdx.x * TM;

  char* cur = smem + SM_EA;
  char* oth = smem + SM_EB;

  // --- prologue: async-load chunk 0 (16 KB) into buffer A ---
  {
    u32 sa = (u32)__cvta_generic_to_shared(cur) + t * 16;
    const float4* gp = (const float4*)g_eh + t;
    #pragma unroll
    for (int i = 0; i < 4; i++)
      cp_async16(sa + i * THREADS * 16, gp + i * THREADS);
    CP_COMMIT();
  }

  const float* zr0 = z + (rowBase + lr0) * D;
  const float* zr1 = z + (rowBase + lr1) * D;

  // --- reference-order zn (verified read pattern + quad butterfly),
  //     straight from global ---
  float zn0, zn1;
  {
    float S0 = 0.f, S1 = 0.f;
    #pragma unroll
    for (int ks = 0; ks < 8; ks++) {
      float v00 = __ldg(&zr0[8 * ks + m]), v01 = __ldg(&zr0[8 * ks + m + 4]);
      float v10 = __ldg(&zr1[8 * ks + m]), v11 = __ldg(&zr1[8 * ks + m + 4]);
      S0 = __fadd_rn(S0, __fmul_rn(v00, v00));
      S0 = __fadd_rn(S0, __fmul_rn(v01, v01));
      S1 = __fadd_rn(S1, __fmul_rn(v10, v10));
      S1 = __fadd_rn(S1, __fmul_rn(v11, v11));
    }
    float T0 = __fadd_rn(S0, __shfl_xor_sync(0xFFFFFFFFu, S0, 2));
    zn0 = __fadd_rn(T0, __shfl_xor_sync(0xFFFFFFFFu, T0, 1));
    float T1 = __fadd_rn(S1, __shfl_xor_sync(0xFFFFFFFFu, S1, 2));
    zn1 = __fadd_rn(T1, __shfl_xor_sync(0xFFFFFFFFu, T1, 1));
  }

  // --- fp16 A-fragments straight from global ---
  u32 ah[4][4];
  #pragma unroll
  for (int s = 0; s < 4; s++) {
    float2 p00 = __ldg((const float2*)&zr0[16 * s + 2 * m]);
    float2 p01 = __ldg((const float2*)&zr0[16 * s + 2 * m + 8]);
    float2 p10 = __ldg((const float2*)&zr1[16 * s + 2 * m]);
    float2 p11 = __ldg((const float2*)&zr1[16 * s + 2 * m + 8]);
    ah[s][0] = h2pack(p00.x, p00.y);
    ah[s][1] = h2pack(p10.x, p10.y);
    ah[s][2] = h2pack(p01.x, p01.y);
    ah[s][3] = h2pack(p11.x, p11.y);
  }

  const u64 zn0p = pack2f(zn0, zn0);
  const u64 zn1p = pack2f(zn1, zn1);
  const u64 ONE2 = pack2f(1.0f, 1.0f);
  const u64 NEG2 = pack2f(NEGINV, NEGINV);   // dot' * -2^-9 == -2*dot (exact)

  float min0v = FLT_MAX, min1v = FLT_MAX;   // best quantized d
  float min0s = FLT_MAX, min1s = FLT_MAX;   // second-best (value only)
  int   min0i = 0,       min1i = 0;

  for (int ch = 0; ch < NCHUNK; ch++) {
    // prefetch next chunk (16 KB) into the other buffer; wait for current
    if (ch + 1 < NCHUNK) {
      u32 sa = (u32)__cvta_generic_to_shared(oth) + t * 16;
      const float4* gp = (const float4*)(g_eh + (size_t)(ch + 1) * 4096) + t;
      #pragma unroll
      for (int i = 0; i < 4; i++)
        cp_async16(sa + i * THREADS * 16, gp + i * THREADS);
      CP_COMMIT();
      CP_WAIT(1);
    } else {
      CP_WAIT(0);
    }
    __syncthreads();

    const uint2* e_h = (const uint2*)cur;
    #pragma unroll
    for (int tt = 0; tt < NTILE; tt++) {
      // B fragments (4 ksteps), conflict-free LDS.64
      uint2 bf[4];
      #pragma unroll
      for (int s = 0; s < 4; s++)
        bf[s] = e_h[(tt * 4 + s) * 32 + lane];

      // split accumulators (2+2) to halve the HMMA dependency chain
      float a0 = 0.f, a1 = 0.f, a2 = 0.f, a3 = 0.f;
      float b0 = 0.f, b1 = 0.f, b2 = 0.f, b3 = 0.f;
      mma_f16(a0, a1, a2, a3, ah[0][0], ah[0][1], ah[0][2], ah[0][3], bf[0].x, bf[0].y);
      mma_f16(b0, b1, b2, b3, ah[1][0], ah[1][1], ah[1][2], ah[1][3], bf[1].x, bf[1].y);
      mma_f16(a0, a1, a2, a3, ah[2][0], ah[2][1], ah[2][2], ah[2][3], bf[2].x, bf[2].y);
      mma_f16(b0, b1, b2, b3, ah[3][0], ah[3][1], ah[3][2], ah[3][3], bf[3].x, bf[3].y);

      // dot' = fl(da+db) (packed); dv = fl(fl(zn+en) + dot'*(-2^-9))
      const int cb = ch * TK + tt * 8 + 2 * m;
      float2 en2 = __ldg((const float2*)(g_en + cb));
      u64 en2p = pack2f(en2.x, en2.y);
      u64 s0 = fmaf2(zn0p, ONE2, en2p);
      u64 s1 = fmaf2(zn1p, ONE2, en2p);
      u64 dot0 = addf2(pack2f(a0, a1), pack2f(b0, b1));
      u64 dot1 = addf2(pack2f(a2, a3), pack2f(b2, b3));
      float dv0, dv1, dv2, dv3;
      unpack2f(fmaf2(dot0, NEG2, s0), dv0, dv1);
      unpack2f(fmaf2(dot1, NEG2, s1), dv2, dv3);

      {
        float lo = fminf(dv0, dv1), hi = fmaxf(dv0, dv1);
        int ip = (dv0 <= dv1) ? cb : cb + 1;          // pair tie -> lower code
        if (lo < min0v) min0i = ip;                   // strict < keeps earliest
        min0s = fminf(fmaxf(min0v, lo), fminf(min0s, hi));
        min0v = fminf(min0v, lo);
      }
      {
        float lo = fminf(dv2, dv3), hi = fmaxf(dv2, dv3);
        int ip = (dv2 <= dv3) ? cb : cb + 1;
        if (lo < min1v) min1i = ip;
        min1s = fminf(fmaxf(min1v, lo), fminf(min1s, hi));
        min1v = fminf(min1v, lo);
      }
    }
    __syncthreads();   // all tiles consumed before this buffer is refilled
    char* tmp = cur; cur = oth; oth = tmp;
  }

  // --- cross-lane top-2 argmin within each quad (tie -> lowest index) ---
  #pragma unroll
  for (int off = 1; off <= 2; off <<= 1) {
    float ov = __shfl_xor_sync(0xFFFFFFFFu, min0v, off);
    int   oi = __shfl_xor_sync(0xFFFFFFFFu, min0i, off);
    float os = __shfl_xor_sync(0xFFFFFFFFu, min0s, off);
    if (ov < min0v || (ov == min0v && oi < min0i)) {
      min0s = fminf(min0v, os); min0v = ov; min0i = oi;
    } else min0s = fminf(min0s, ov);
    ov = __shfl_xor_sync(0xFFFFFFFFu, min1v, off);
    oi = __shfl_xor_sync(0xFFFFFFFFu, min1i, off);
    os = __shfl_xor_sync(0xFFFFFFFFu, min1s, off);
    if (ov < min1v || (ov == min1v && oi < min1i)) {
      min1s = fminf(min1v, os); min1v = ov; min1i = oi;
    } else min1s = fminf(min1s, ov);
  }

  float contrib = 0.f;
  if (m == 0) {
    sidx[lr0] = min0i; sidx[lr1] = min1i;
    out_idx[rowBase + lr0] = (float)min0i;
    out_idx[rowBase + lr1] = (float)min1i;
    contrib = min0v + min1v;   // quantized d_min values
    // risky rows: top-2 gap within 4e-5 ABSOLUTE -> exact rescore later
    if (min0s - min0v <= 4e-5f) {
      int p = atomicAdd(&g_risky_count, 1);
      g_risky[p] = (int)(rowBase + lr0);
    }
    if (min1s - min1v <= 4e-5f) {
      int p = atomicAdd(&g_risky_count, 1);
      g_risky[p] = (int)(rowBase + lr1);
    }
  }
  // warp sum of loss contributions
  #pragma unroll
  for (int o = 16; o > 0; o >>= 1) contrib += __shfl_xor_sync(0xFFFFFFFFu, contrib, o);
  if (lane == 0) sred[w] = contrib;
  __syncthreads();
  if (t == 0) {
    float tot = 0.f;
    #pragma unroll
    for (int i = 0; i < 8; i++) tot += sred[i];
    g_partial[blockIdx.x] = tot;
  }

  // coalesced z_q gather: 16 float4 lanes per row
  for (int j = t; j < TM * (D / 4); j += THREADS) {
    int r2 = j >> 4, p = j & 15;
    ((float4*)(out_zq + (rowBase + r2) * D))[p] =
        ((const float4*)(emb + (size_t)sidx[r2] * D))[p];
  }
}

// ---------------------------------------------------------------------------
// Kernel 1b: exact rescore of risky rows — coalesced (validated round 13).
// ---------------------------------------------------------------------------
__global__ void __launch_bounds__(256, 4)
vq_fix_kernel(const float* __restrict__ z, const float* __restrict__ emb,
              float* __restrict__ out_zq, float* __restrict__ out_idx) {
  __shared__ float zrow[8][D];
  const int wl = threadIdx.x >> 5, lane = threadIdx.x & 31;
  const int q = lane >> 2, m = lane & 3;
  const int wg = blockIdx.x * 8 + wl;
  const int nw = gridDim.x * 8;
  const int cnt = g_risky_count;

  for (int i = wg; i < cnt; i += nw) {
    const int row = g_risky[i];
    ((float2*)zrow[wl])[lane] = ((const float2*)(z + (size_t)row * D))[lane];
    __syncwarp();

    const float zn = ref_sqnorm_seq(zrow[wl]);

    float zf[16];
    #pragma unroll
    for (int d2 = 0; d2 < 16; d2++) zf[d2] = zrow[wl][m * 16 + d2];

    float bestv = FLT_MAX; int besti = 0;
    for (int c0 = 0; c0 < KCODES; c0 += 8) {
      const int code = c0 + q;
      const float4* ep = (const float4*)(emb + (size_t)code * D + m * 16);
      float p = 0.f;
      #pragma unroll
      for (int v4 = 0; v4 < 4; v4++) {
        float4 ev = __ldg(ep + v4);
        p = __fmaf_rn(zf[v4 * 4 + 0], ev.x, p);
        p = __fmaf_rn(zf[v4 * 4 + 1], ev.y, p);
        p = __fmaf_rn(zf[v4 * 4 + 2], ev.z, p);
        p = __fmaf_rn(zf[v4 * 4 + 3], ev.w, p);
      }
      p += __shfl_xor_sync(0xFFFFFFFFu, p, 1);
      p += __shfl_xor_sync(0xFFFFFFFFu, p, 2);
      float dv = __fsub_rn(__fadd_rn(zn, __ldg(&g_en[code])), __fadd_rn(p, p));
      if (dv < bestv) { bestv = dv; besti = code; }  // codes ascending per quad
    }
    #pragma unroll
    for (int off = 4; off <= 16; off <<= 1) {
      float ov = __shfl_xor_sync(0xFFFFFFFFu, bestv, off);
      int   oi = __shfl_xor_sync(0xFFFFFFFFu, besti, off);
      if (ov < bestv || (ov == bestv && oi < besti)) { bestv = ov; besti = oi; }
    }
    if (lane == 0) out_idx[row] = (float)besti;
    if (lane < 16)
      ((float4*)(out_zq + (size_t)row * D))[lane] =
          ((const float4*)(emb + (size_t)besti * D))[lane];
    __syncwarp();
  }
}

// ---------------------------------------------------------------------------
// Kernel 2: deterministic loss reduction (double accumulation)
// ---------------------------------------------------------------------------
__global__ void vq_finish_kernel(float* __restrict__ out_loss, int nb, long long nd) {
  int t = threadIdx.x;
  double v = (t < nb) ? (double)g_partial[t] : 0.0;
  #pragma unroll
  for (int o = 16; o > 0; o >>= 1) v += __shfl_xor_sync(0xFFFFFFFFu, v, o);
  __shared__ double red[32];
  if ((t & 31) == 0) red[t >> 5] = v;
  __syncthreads();
  if (t < 32) {
    double w = (t < (int)(blockDim.x >> 5)) ? red[t] : 0.0;
    #pragma unroll
    for (int o = 16; o > 0; o >>= 1) w += __shfl_xor_sync(0xFFFFFFFFu, w, o);
    if (t == 0) out_loss[0] = (float)(1.25 * w / (double)nd);
  }
}

// ---------------------------------------------------------------------------
extern "C" void kernel_launch(void* const* d_in, const int* in_sizes, int n_in,
                              void* d_out, int out_size) {
  const float* z   = (const float*)d_in[0];   // [N,1,64] fp32
  const float* emb = (const float*)d_in[1];   // [1024,64] fp32
  float* out = (float*)d_out;

  const int N = in_sizes[0] / D;              // 131072
  float* out_zq   = out;                      // [N*D]
  float* out_idx  = out + (size_t)N * D;      // [N] (indices as float)
  float* out_loss = out_idx + N;              // [1]

  vq_prep_kernel<<<(KCODES + 127) / 128, 128>>>(emb);

  cudaFuncSetAttribute(vq_main_kernel,
                       cudaFuncAttributeMaxDynamicSharedMemorySize, SM_TOTAL);
  vq_main_kernel<<<N / TM, THREADS, SM_TOTAL>>>(z, emb, out_zq, out_idx);

  vq_fix_kernel<<<128, 256>>>(z, emb, out_zq, out_idx);

  vq_finish_kernel<<<1, 1024>>>(out_loss, N / TM, (long long)N * D);
}